// round 3
// baseline (speedup 1.0000x reference)
#include <cuda_runtime.h>
#include <math.h>
#include <float.h>

#define Nn   50000
#define FIN  64
#define Hh   256
#define Ee   800000
#define Gg   2048
#define Ll   4
#define Tt   4
#define EPSc 1e-5f

// ---------------- scratch: __device__ globals, referenced by symbol only ----------------
__device__ float g_h [Nn * Hh];        // node features (updated per layer)
__device__ float g_hW[Nn * Hh];        // h @ W per layer
__device__ float g_isd[Nn];            // 1/sqrt(deg)
__device__ int   g_cnt[Nn];            // in-degree (edges only)
__device__ int   g_off[Nn + 1];        // CSR offsets
__device__ int   g_cur[Nn];            // CSR fill cursors
__device__ int   g_csr[Ee];            // CSR src indices
__device__ int   g_part[64];           // scan partials
__device__ float g_pool[Gg * 2 * Hh];  // [G, 2H] mean|max
__device__ float g_f1[Gg * Hh];
__device__ float g_f2[Gg * (Hh / 2)];

// ---------------- degree / CSR construction ----------------
__global__ void k_zero_cnt() {
    int i = blockIdx.x * blockDim.x + threadIdx.x;
    if (i < Nn) g_cnt[i] = 0;
}

// edge_index is INT32 (JAX x64 disabled downgrades int64 -> int32)
__global__ void k_count_edges(const int* __restrict__ ei) {
    int e = blockIdx.x * blockDim.x + threadIdx.x;
    if (e < Ee) {
        int d = ei[Ee + e];
        atomicAdd(&g_cnt[d], 1);
    }
}

__global__ void k_scan_block() {
    __shared__ int s[1024];
    int gid = blockIdx.x * 1024 + threadIdx.x;
    int v = (gid < Nn) ? g_cnt[gid] : 0;
    s[threadIdx.x] = v;
    for (int d = 1; d < 1024; d <<= 1) {
        __syncthreads();
        int t = (threadIdx.x >= d) ? s[threadIdx.x - d] : 0;
        __syncthreads();
        s[threadIdx.x] += t;
    }
    __syncthreads();
    if (gid < Nn) g_off[gid] = s[threadIdx.x] - v;   // exclusive
    if (threadIdx.x == 1023) g_part[blockIdx.x] = s[1023];
}

__global__ void k_scan_part(int nb) {
    if (threadIdx.x == 0 && blockIdx.x == 0) {
        int acc = 0;
        for (int i = 0; i < nb; i++) { int t = g_part[i]; g_part[i] = acc; acc += t; }
    }
}

__global__ void k_scan_add() {
    int gid = blockIdx.x * 1024 + threadIdx.x;
    if (gid < Nn) {
        int v = g_off[gid] + g_part[blockIdx.x];
        g_off[gid] = v;
        g_cur[gid] = v;
    }
    if (gid == 0) g_off[Nn] = Ee;
}

__global__ void k_isd() {
    int i = blockIdx.x * blockDim.x + threadIdx.x;
    if (i < Nn) g_isd[i] = rsqrtf(1.0f + (float)g_cnt[i]);
}

__global__ void k_csr_fill(const int* __restrict__ ei) {
    int e = blockIdx.x * blockDim.x + threadIdx.x;
    if (e < Ee) {
        int s = ei[e];
        int d = ei[Ee + e];
        int p = atomicAdd(&g_cur[d], 1);
        g_csr[p] = s;
    }
}

// ---------------- SGEMM: C[M,N] = A[M,K] @ B[K,N] (+bias, relu) ----------------
//   sel 0: A = Aext (input x), C = g_h
//   sel 1: A = g_h,            C = g_hW
//   sel 2: A = g_pool,         C = g_f1
//   sel 3: A = g_f1,           C = g_f2
// BM=BN=64, BK=16, 256 threads, 4x4 per thread. Requires K%16==0, N%64==0.
__global__ void k_sgemm(const float* __restrict__ Aext, const float* __restrict__ B,
                        const float* __restrict__ bias,
                        int M, int N, int K, int doRelu, int sel) {
    const float* A = (sel == 0) ? Aext : (sel == 1) ? g_h : (sel == 2) ? g_pool : g_f1;
    float*       C = (sel == 0) ? g_h  : (sel == 1) ? g_hW : (sel == 2) ? g_f1  : g_f2;

    __shared__ float As[16][64];
    __shared__ float Bs[16][68];

    int tid = threadIdx.x;
    int m0 = blockIdx.y * 64, n0 = blockIdx.x * 64;
    int tr = tid >> 4, tc = tid & 15;

    int arow = tid >> 2;          // 0..63
    int aq   = (tid & 3) * 4;     // 0,4,8,12
    int brow = tid >> 4;          // 0..15
    int bq   = (tid & 15) * 4;    // 0..60

    float acc[4][4];
    #pragma unroll
    for (int i = 0; i < 4; i++)
        #pragma unroll
        for (int j = 0; j < 4; j++) acc[i][j] = 0.f;

    for (int k0 = 0; k0 < K; k0 += 16) {
        float4 av;
        if (m0 + arow < M)
            av = *reinterpret_cast<const float4*>(&A[(size_t)(m0 + arow) * K + k0 + aq]);
        else
            av = make_float4(0.f, 0.f, 0.f, 0.f);
        As[aq + 0][arow] = av.x;
        As[aq + 1][arow] = av.y;
        As[aq + 2][arow] = av.z;
        As[aq + 3][arow] = av.w;

        float4 bv = *reinterpret_cast<const float4*>(&B[(size_t)(k0 + brow) * N + n0 + bq]);
        Bs[brow][bq + 0] = bv.x;
        Bs[brow][bq + 1] = bv.y;
        Bs[brow][bq + 2] = bv.z;
        Bs[brow][bq + 3] = bv.w;
        __syncthreads();

        #pragma unroll
        for (int k = 0; k < 16; k++) {
            float ar[4], br[4];
            #pragma unroll
            for (int i = 0; i < 4; i++) ar[i] = As[k][tr * 4 + i];
            #pragma unroll
            for (int j = 0; j < 4; j++) br[j] = Bs[k][tc * 4 + j];
            #pragma unroll
            for (int i = 0; i < 4; i++)
                #pragma unroll
                for (int j = 0; j < 4; j++) acc[i][j] = fmaf(ar[i], br[j], acc[i][j]);
        }
        __syncthreads();
    }

    #pragma unroll
    for (int i = 0; i < 4; i++) {
        int m = m0 + tr * 4 + i;
        if (m >= M) continue;
        #pragma unroll
        for (int j = 0; j < 4; j++) {
            int n = n0 + tc * 4 + j;
            float v = acc[i][j];
            if (bias) v += bias[n];
            if (doRelu) v = fmaxf(v, 0.f);
            C[(size_t)m * N + n] = v;
        }
    }
}

// ---------------- fused aggregation + bias + BN + ReLU + residual ----------------
// one block per dst node, 256 threads = 256 features
__global__ void k_agg_fused(const float* __restrict__ bias, const float* __restrict__ gamma,
                            const float* __restrict__ beta, const float* __restrict__ mean,
                            const float* __restrict__ var) {
    int v = blockIdx.x;
    int t = threadIdx.x;
    float idv = g_isd[v];
    float acc = g_hW[(size_t)v * Hh + t] * idv * idv;   // self-loop term

    int s0 = g_off[v], s1 = g_off[v + 1];
    for (int j = s0; j < s1; j++) {
        int u = g_csr[j];                        // broadcast across block
        float w = g_isd[u] * idv;
        acc = fmaf(g_hW[(size_t)u * Hh + t], w, acc);
    }

    acc += bias[t];
    float sc = gamma[t] * rsqrtf(var[t] + EPSc);
    float y = (acc - mean[t]) * sc + beta[t];
    y = fmaxf(y, 0.f);
    g_h[(size_t)v * Hh + t] = y + g_h[(size_t)v * Hh + t];
}

// ---------------- pooling: mean + max per graph (batch is sorted int32) ----------------
__global__ void k_pool(const int* __restrict__ batch) {
    __shared__ int sb[2];
    int grp = blockIdx.x, t = threadIdx.x;
    if (t < 2) {
        int key = grp + t;
        int lo = 0, hi = Nn;
        while (lo < hi) {
            int mid = (lo + hi) >> 1;
            if (batch[mid] < key) lo = mid + 1; else hi = mid;
        }
        sb[t] = lo;
    }
    __syncthreads();
    int s = sb[0], e = sb[1];
    float sum = 0.f, mx = -FLT_MAX;
    for (int i = s; i < e; i++) {
        float v = g_h[(size_t)i * Hh + t];
        sum += v;
        mx = fmaxf(mx, v);
    }
    float c = (float)(e - s);
    g_pool[(size_t)grp * (2 * Hh) + t]      = sum / fmaxf(c, 1.f);
    g_pool[(size_t)grp * (2 * Hh) + Hh + t] = mx;
}

// ---------------- tiny final GEMM [G,128] @ [128,4] ----------------
__global__ void k_head3(const float* __restrict__ W, const float* __restrict__ b,
                        float* __restrict__ out) {
    int idx = blockIdx.x * blockDim.x + threadIdx.x;
    if (idx >= Gg * Tt) return;
    int r = idx >> 2, c = idx & 3;
    float acc = b[c];
    const float* row = &g_f2[(size_t)r * 128];
    #pragma unroll 8
    for (int k = 0; k < 128; k++) acc = fmaf(row[k], W[k * 4 + c], acc);
    out[idx] = acc;
}

// ---------------- launch: kernel launches ONLY ----------------
extern "C" void kernel_launch(void* const* d_in, const int* in_sizes, int n_in,
                              void* d_out, int out_size) {
    const float* x     = (const float*)d_in[0];
    const int*   ei    = (const int*)d_in[1];     // int32 (JAX x64 off)
    const int*   batch = (const int*)d_in[2];     // int32
    const float* projW = (const float*)d_in[3];
    const float* projb = (const float*)d_in[4];
    const float* convW = (const float*)d_in[5];   // [L,H,H]
    const float* convb = (const float*)d_in[6];   // [L,H]
    const float* gamma = (const float*)d_in[7];
    const float* beta  = (const float*)d_in[8];
    const float* mean  = (const float*)d_in[9];
    const float* var   = (const float*)d_in[10];
    const float* W1 = (const float*)d_in[11];
    const float* b1 = (const float*)d_in[12];
    const float* W2 = (const float*)d_in[13];
    const float* b2 = (const float*)d_in[14];
    const float* W3 = (const float*)d_in[15];
    const float* b3 = (const float*)d_in[16];
    float* out = (float*)d_out;

    const int SCAN_B = (Nn + 1023) / 1024;   // 49

    // CSR + degree norm
    k_zero_cnt   <<<(Nn + 255) / 256, 256>>>();
    k_count_edges<<<(Ee + 255) / 256, 256>>>(ei);
    k_scan_block <<<SCAN_B, 1024>>>();
    k_scan_part  <<<1, 32>>>(SCAN_B);
    k_scan_add   <<<SCAN_B, 1024>>>();
    k_isd        <<<(Nn + 255) / 256, 256>>>();
    k_csr_fill   <<<(Ee + 255) / 256, 256>>>(ei);

    // input projection: h = relu(x @ projW + projb)
    k_sgemm<<<dim3(Hh / 64, (Nn + 63) / 64), 256>>>(x, projW, projb, Nn, Hh, FIN, 1, 0);

    // 4 GCN layers
    for (int l = 0; l < Ll; l++) {
        k_sgemm<<<dim3(Hh / 64, (Nn + 63) / 64), 256>>>(
            nullptr, convW + (size_t)l * Hh * Hh, nullptr, Nn, Hh, Hh, 0, 1);
        k_agg_fused<<<Nn, 256>>>(convb + l * Hh, gamma + l * Hh, beta + l * Hh,
                                 mean + l * Hh, var + l * Hh);
    }

    // pooling + head
    k_pool<<<Gg, 256>>>(batch);
    k_sgemm<<<dim3(Hh / 64, Gg / 64), 256>>>(nullptr, W1, b1, Gg, Hh, 2 * Hh, 1, 2);
    k_sgemm<<<dim3((Hh / 2) / 64, Gg / 64), 256>>>(nullptr, W2, b2, Gg, Hh / 2, Hh, 1, 3);
    k_head3<<<(Gg * Tt + 255) / 256, 256>>>(W3, b3, out);
}

// round 5
// speedup vs baseline: 1.3719x; 1.3719x over previous
#include <cuda_runtime.h>
#include <cuda_bf16.h>
#include <math.h>
#include <float.h>
#include <stdint.h>

#define Nn   50000
#define FIN  64
#define Hh   256
#define Ee   800000
#define Gg   2048
#define Ll   4
#define Tt   4
#define EPSc 1e-5f

#define MTILES ((Nn + 127) / 128)   // 391
#define Mpad   (MTILES * 128)       // 50048

// ---------------- scratch ----------------
__device__ __align__(16) float g_h [Nn * Hh];
__device__ __align__(16) float g_hW[(size_t)Mpad * Hh];
__device__ float g_isd[Nn];
__device__ int   g_cnt[Nn];
__device__ int   g_off[Nn + 1];
__device__ int   g_cur[Nn];
__device__ int   g_csr[Ee];
__device__ int   g_part[64];
__device__ __align__(16) float g_pool[Gg * 2 * Hh];
__device__ __align__(16) float g_f1[Gg * Hh];
__device__ __align__(16) float g_f2[Gg * (Hh / 2)];
// bf16 split of node features (A operand): [Mpad][H]; pad rows stay zero
__device__ __align__(16) __nv_bfloat16 g_Ahi[(size_t)Mpad * Hh];
__device__ __align__(16) __nv_bfloat16 g_Alo[(size_t)Mpad * Hh];
// bf16 split conv weights, [L][K][N] (same layout as input)
__device__ __align__(16) __nv_bfloat16 g_Bhi[Ll * Hh * Hh];
__device__ __align__(16) __nv_bfloat16 g_Blo[Ll * Hh * Hh];

// ---------------- asm helpers ----------------
__device__ __forceinline__ uint32_t smem_u32(const void* p) {
    uint32_t a;
    asm("{ .reg .u64 t; cvta.to.shared.u64 t, %1; cvt.u32.u64 %0, t; }" : "=r"(a) : "l"(p));
    return a;
}
#define CPA(dst, src) \
    asm volatile("cp.async.cg.shared.global [%0], [%1], 16;" :: "r"(dst), "l"(src) : "memory")
#define LDSM4(r, addr) \
    asm volatile("ldmatrix.sync.aligned.m8n8.x4.shared.b16 {%0,%1,%2,%3}, [%4];" \
        : "=r"((r)[0]), "=r"((r)[1]), "=r"((r)[2]), "=r"((r)[3]) : "r"(addr))
#define LDSM4T(r, addr) \
    asm volatile("ldmatrix.sync.aligned.m8n8.x4.trans.shared.b16 {%0,%1,%2,%3}, [%4];" \
        : "=r"((r)[0]), "=r"((r)[1]), "=r"((r)[2]), "=r"((r)[3]) : "r"(addr))
#define MMA16816(c, a, b) \
    asm volatile("mma.sync.aligned.m16n8k16.row.col.f32.bf16.bf16.f32 " \
        "{%0,%1,%2,%3}, {%4,%5,%6,%7}, {%8,%9}, {%0,%1,%2,%3};" \
        : "+f"((c)[0]), "+f"((c)[1]), "+f"((c)[2]), "+f"((c)[3]) \
        : "r"((a)[0]), "r"((a)[1]), "r"((a)[2]), "r"((a)[3]), "r"((b)[0]), "r"((b)[1]))

// ---------------- degree / CSR ----------------
__global__ void k_zero_cnt() {
    int i = blockIdx.x * blockDim.x + threadIdx.x;
    if (i < Nn) g_cnt[i] = 0;
}
__global__ void k_count_edges(const int* __restrict__ ei) {
    int e = blockIdx.x * blockDim.x + threadIdx.x;
    if (e < Ee) atomicAdd(&g_cnt[ei[Ee + e]], 1);
}
__global__ void k_scan_block() {
    __shared__ int s[1024];
    int gid = blockIdx.x * 1024 + threadIdx.x;
    int v = (gid < Nn) ? g_cnt[gid] : 0;
    s[threadIdx.x] = v;
    for (int d = 1; d < 1024; d <<= 1) {
        __syncthreads();
        int t = (threadIdx.x >= d) ? s[threadIdx.x - d] : 0;
        __syncthreads();
        s[threadIdx.x] += t;
    }
    __syncthreads();
    if (gid < Nn) g_off[gid] = s[threadIdx.x] - v;
    if (threadIdx.x == 1023) g_part[blockIdx.x] = s[1023];
}
__global__ void k_scan_part(int nb) {
    if (threadIdx.x == 0 && blockIdx.x == 0) {
        int acc = 0;
        for (int i = 0; i < nb; i++) { int t = g_part[i]; g_part[i] = acc; acc += t; }
    }
}
__global__ void k_scan_add() {
    int gid = blockIdx.x * 1024 + threadIdx.x;
    if (gid < Nn) {
        int v = g_off[gid] + g_part[blockIdx.x];
        g_off[gid] = v;
        g_cur[gid] = v;
    }
    if (gid == 0) g_off[Nn] = Ee;
}
__global__ void k_isd() {
    int i = blockIdx.x * blockDim.x + threadIdx.x;
    if (i < Nn) g_isd[i] = rsqrtf(1.0f + (float)g_cnt[i]);
}
__global__ void k_csr_fill(const int* __restrict__ ei) {
    int e = blockIdx.x * blockDim.x + threadIdx.x;
    if (e < Ee) {
        int p = atomicAdd(&g_cur[ei[Ee + e]], 1);
        g_csr[p] = ei[e];
    }
}

// ---------------- W split: [L][K][N] fp32 -> bf16 hi/lo (same layout) ----------------
__global__ void k_convW(const float* __restrict__ convW) {
    int idx = blockIdx.x * blockDim.x + threadIdx.x;
    if (idx >= Ll * Hh * Hh) return;
    float w = convW[idx];
    __nv_bfloat16 hi = __float2bfloat16(w);
    g_Bhi[idx] = hi;
    g_Blo[idx] = __float2bfloat16(w - __bfloat162float(hi));
}

// ---------------- bf16x3 mma.sync GEMM: g_hW = h @ W (fp32-accurate) ----------------
// CTA 128x128, K=256 in 16 chunks, double-buffered cp.async.
// SMEM: A hi/lo rows padded to 48B; B hi/lo rows padded to 272B (conflict-free ldmatrix).
//   A_HI: [0, 12288)  (2 stages x 6144)     A_LO: [12288, 24576)
//   B_HI: [24576, 33280) (2 x 4352)          B_LO: [33280, 41984)
__global__ __launch_bounds__(256) void k_gemm_mma(int layer) {
    __shared__ __align__(16) unsigned char smraw[41984];
    const int tid = threadIdx.x, lane = tid & 31, wid = tid >> 5;
    const int warp_m = wid & 3, warp_n = wid >> 2;
    const int m0 = blockIdx.x * 128, n0 = blockIdx.y * 128;
    const uint32_t sb = smem_u32(smraw);

    const __nv_bfloat16* Bh = g_Bhi + (size_t)layer * Hh * Hh;
    const __nv_bfloat16* Bl = g_Blo + (size_t)layer * Hh * Hh;

    // cp.async per-thread slots: A: 256 chunks (128 rows x 2), B: 256 (16 rows x 16)
    const int ar = tid >> 1, ac = tid & 1;
    const int brr = tid >> 4, bcc = tid & 15;
    const __nv_bfloat16* srcAh = g_Ahi + (size_t)(m0 + ar) * Hh + ac * 8;
    const __nv_bfloat16* srcAl = g_Alo + (size_t)(m0 + ar) * Hh + ac * 8;
    const __nv_bfloat16* srcBh = Bh + (size_t)brr * Hh + n0 + bcc * 8;
    const __nv_bfloat16* srcBl = Bl + (size_t)brr * Hh + n0 + bcc * 8;
    const uint32_t dAh = sb + ar * 48 + ac * 16;
    const uint32_t dAl = dAh + 12288;
    const uint32_t dBh = sb + 24576 + brr * 272 + bcc * 16;
    const uint32_t dBl = dBh + 8704;

#define LOAD_STAGE(s, kt) do { \
        CPA(dAh + (s) * 6144, srcAh + (kt) * 16); \
        CPA(dAl + (s) * 6144, srcAl + (kt) * 16); \
        CPA(dBh + (s) * 4352, srcBh + (size_t)(kt) * 16 * Hh); \
        CPA(dBl + (s) * 4352, srcBl + (size_t)(kt) * 16 * Hh); \
        asm volatile("cp.async.commit_group;" ::: "memory"); \
    } while (0)

    float acc[2][8][4];
    #pragma unroll
    for (int i = 0; i < 2; i++)
        #pragma unroll
        for (int j = 0; j < 8; j++)
            #pragma unroll
            for (int q = 0; q < 4; q++) acc[i][j][q] = 0.f;

    // ldmatrix lane base addresses
    const uint32_t aoff = sb + (warp_m * 32 + (lane & 15)) * 48 + (lane >> 4) * 16;
    const uint32_t boff = sb + 24576 + (lane & 15) * 272 + (warp_n * 8 + (lane >> 4)) * 16;

    LOAD_STAGE(0, 0);
    LOAD_STAGE(1, 1);

    #pragma unroll
    for (int kt = 0; kt < 16; kt++) {
        const int s = kt & 1;
        if (kt < 15) asm volatile("cp.async.wait_group 1;" ::: "memory");
        else         asm volatile("cp.async.wait_group 0;" ::: "memory");
        __syncthreads();

        uint32_t ah[2][4], al[2][4], bh[4][4], bl[4][4];
        #pragma unroll
        for (int mt = 0; mt < 2; mt++) {
            LDSM4(ah[mt], aoff + s * 6144 + mt * 768);
            LDSM4(al[mt], aoff + 12288 + s * 6144 + mt * 768);
        }
        #pragma unroll
        for (int nt = 0; nt < 4; nt++) {
            LDSM4T(bh[nt], boff + s * 4352 + nt * 32);
            LDSM4T(bl[nt], boff + 8704 + s * 4352 + nt * 32);
        }
        #pragma unroll
        for (int mt = 0; mt < 2; mt++)
            #pragma unroll
            for (int nt = 0; nt < 4; nt++)
                #pragma unroll
                for (int nb = 0; nb < 2; nb++) {
                    float* c = acc[mt][nt * 2 + nb];
                    MMA16816(c, ah[mt], &bh[nt][nb * 2]);
                    MMA16816(c, ah[mt], &bl[nt][nb * 2]);
                    MMA16816(c, al[mt], &bh[nt][nb * 2]);
                }
        __syncthreads();
        if (kt + 2 < 16) LOAD_STAGE(s, kt + 2);
    }
#undef LOAD_STAGE

    // epilogue: warp tile 32x64 -> g_hW (pad rows are harmless, within Mpad)
    #pragma unroll
    for (int mt = 0; mt < 2; mt++) {
        int r0 = m0 + warp_m * 32 + mt * 16 + (lane >> 2);
        #pragma unroll
        for (int j = 0; j < 8; j++) {
            int n = n0 + warp_n * 64 + j * 8 + (lane & 3) * 2;
            float2 v0 = {acc[mt][j][0], acc[mt][j][1]};
            float2 v1 = {acc[mt][j][2], acc[mt][j][3]};
            *(float2*)&g_hW[(size_t)r0 * Hh + n] = v0;
            *(float2*)&g_hW[(size_t)(r0 + 8) * Hh + n] = v1;
        }
    }
}

// ---------------- SIMT SGEMM (proj + head) ----------------
//   sel 0: A = Aext (x), C = g_h (+ bf16 hi/lo split emit)
//   sel 2: A = g_pool,   C = g_f1
//   sel 3: A = g_f1,     C = g_f2
__global__ void k_sgemm(const float* __restrict__ Aext, const float* __restrict__ B,
                        const float* __restrict__ bias,
                        int M, int N, int K, int doRelu, int sel) {
    const float* A = (sel == 0) ? Aext : (sel == 2) ? g_pool : g_f1;
    float*       C = (sel == 0) ? g_h  : (sel == 2) ? g_f1  : g_f2;

    __shared__ float As[16][64];
    __shared__ float Bs[16][68];

    int tid = threadIdx.x;
    int m0 = blockIdx.y * 64, n0 = blockIdx.x * 64;
    int tr = tid >> 4, tc = tid & 15;
    int arow = tid >> 2, aq = (tid & 3) * 4;
    int brow = tid >> 4, bq = (tid & 15) * 4;

    float acc[4][4];
    #pragma unroll
    for (int i = 0; i < 4; i++)
        #pragma unroll
        for (int j = 0; j < 4; j++) acc[i][j] = 0.f;

    for (int k0 = 0; k0 < K; k0 += 16) {
        float4 av;
        if (m0 + arow < M)
            av = *reinterpret_cast<const float4*>(&A[(size_t)(m0 + arow) * K + k0 + aq]);
        else
            av = make_float4(0.f, 0.f, 0.f, 0.f);
        As[aq + 0][arow] = av.x;
        As[aq + 1][arow] = av.y;
        As[aq + 2][arow] = av.z;
        As[aq + 3][arow] = av.w;

        float4 bv = *reinterpret_cast<const float4*>(&B[(size_t)(k0 + brow) * N + n0 + bq]);
        Bs[brow][bq + 0] = bv.x;
        Bs[brow][bq + 1] = bv.y;
        Bs[brow][bq + 2] = bv.z;
        Bs[brow][bq + 3] = bv.w;
        __syncthreads();

        #pragma unroll
        for (int k = 0; k < 16; k++) {
            float arr[4], br[4];
            #pragma unroll
            for (int i = 0; i < 4; i++) arr[i] = As[k][tr * 4 + i];
            #pragma unroll
            for (int j = 0; j < 4; j++) br[j] = Bs[k][tc * 4 + j];
            #pragma unroll
            for (int i = 0; i < 4; i++)
                #pragma unroll
                for (int j = 0; j < 4; j++) acc[i][j] = fmaf(arr[i], br[j], acc[i][j]);
        }
        __syncthreads();
    }

    #pragma unroll
    for (int i = 0; i < 4; i++) {
        int m = m0 + tr * 4 + i;
        if (m >= M) continue;
        #pragma unroll
        for (int j = 0; j < 4; j++) {
            int n = n0 + tc * 4 + j;
            float v = acc[i][j];
            if (bias) v += bias[n];
            if (doRelu) v = fmaxf(v, 0.f);
            C[(size_t)m * N + n] = v;
            if (sel == 0) {   // proj: emit bf16 split of h for the mma GEMM
                __nv_bfloat16 hi = __float2bfloat16(v);
                g_Ahi[(size_t)m * Hh + n] = hi;
                g_Alo[(size_t)m * Hh + n] = __float2bfloat16(v - __bfloat162float(hi));
            }
        }
    }
}

// ---------------- fused aggregation + bias + BN + ReLU + residual (+ bf16 split) ----------------
__global__ void k_agg_fused(const float* __restrict__ bias, const float* __restrict__ gamma,
                            const float* __restrict__ beta, const float* __restrict__ mean,
                            const float* __restrict__ var) {
    int v = blockIdx.x;
    int t = threadIdx.x;
    float idv = g_isd[v];
    float acc = g_hW[(size_t)v * Hh + t] * idv * idv;

    int s0 = g_off[v], s1 = g_off[v + 1];
    for (int j = s0; j < s1; j++) {
        int u = g_csr[j];
        float w = g_isd[u] * idv;
        acc = fmaf(g_hW[(size_t)u * Hh + t], w, acc);
    }

    acc += bias[t];
    float sc = gamma[t] * rsqrtf(var[t] + EPSc);
    float y = (acc - mean[t]) * sc + beta[t];
    y = fmaxf(y, 0.f);
    float o = y + g_h[(size_t)v * Hh + t];
    g_h[(size_t)v * Hh + t] = o;
    __nv_bfloat16 hi = __float2bfloat16(o);
    g_Ahi[(size_t)v * Hh + t] = hi;
    g_Alo[(size_t)v * Hh + t] = __float2bfloat16(o - __bfloat162float(hi));
}

// ---------------- pooling ----------------
__global__ void k_pool(const int* __restrict__ batch) {
    __shared__ int sbb[2];
    int grp = blockIdx.x, t = threadIdx.x;
    if (t < 2) {
        int key = grp + t;
        int lo = 0, hi = Nn;
        while (lo < hi) {
            int mid = (lo + hi) >> 1;
            if (batch[mid] < key) lo = mid + 1; else hi = mid;
        }
        sbb[t] = lo;
    }
    __syncthreads();
    int s = sbb[0], e = sbb[1];
    float sum = 0.f, mx = -FLT_MAX;
    for (int i = s; i < e; i++) {
        float v = g_h[(size_t)i * Hh + t];
        sum += v;
        mx = fmaxf(mx, v);
    }
    float c = (float)(e - s);
    g_pool[(size_t)grp * (2 * Hh) + t]      = sum / fmaxf(c, 1.f);
    g_pool[(size_t)grp * (2 * Hh) + Hh + t] = mx;
}

// ---------------- final tiny GEMM ----------------
__global__ void k_head3(const float* __restrict__ W, const float* __restrict__ b,
                        float* __restrict__ out) {
    int idx = blockIdx.x * blockDim.x + threadIdx.x;
    if (idx >= Gg * Tt) return;
    int r = idx >> 2, c = idx & 3;
    float acc = b[c];
    const float* row = &g_f2[(size_t)r * 128];
    #pragma unroll 8
    for (int k = 0; k < 128; k++) acc = fmaf(row[k], W[k * 4 + c], acc);
    out[idx] = acc;
}

// ---------------- launch ----------------
extern "C" void kernel_launch(void* const* d_in, const int* in_sizes, int n_in,
                              void* d_out, int out_size) {
    const float* x     = (const float*)d_in[0];
    const int*   ei    = (const int*)d_in[1];
    const int*   batch = (const int*)d_in[2];
    const float* projW = (const float*)d_in[3];
    const float* projb = (const float*)d_in[4];
    const float* convW = (const float*)d_in[5];
    const float* convb = (const float*)d_in[6];
    const float* gamma = (const float*)d_in[7];
    const float* beta  = (const float*)d_in[8];
    const float* mean  = (const float*)d_in[9];
    const float* var   = (const float*)d_in[10];
    const float* W1 = (const float*)d_in[11];
    const float* b1 = (const float*)d_in[12];
    const float* W2 = (const float*)d_in[13];
    const float* b2 = (const float*)d_in[14];
    const float* W3 = (const float*)d_in[15];
    const float* b3 = (const float*)d_in[16];
    float* out = (float*)d_out;

    const int SCAN_B = (Nn + 1023) / 1024;

    // CSR + degree norm + weight split
    k_zero_cnt   <<<(Nn + 255) / 256, 256>>>();
    k_count_edges<<<(Ee + 255) / 256, 256>>>(ei);
    k_scan_block <<<SCAN_B, 1024>>>();
    k_scan_part  <<<1, 32>>>(SCAN_B);
    k_scan_add   <<<SCAN_B, 1024>>>();
    k_isd        <<<(Nn + 255) / 256, 256>>>();
    k_csr_fill   <<<(Ee + 255) / 256, 256>>>(ei);
    k_convW      <<<(Ll * Hh * Hh + 255) / 256, 256>>>(convW);

    // projection (emits g_h + bf16 split)
    k_sgemm<<<dim3(Hh / 64, (Nn + 63) / 64), 256>>>(x, projW, projb, Nn, Hh, FIN, 1, 0);

    // 4 GCN layers: mma.sync bf16x3 GEMM + fused aggregation epilogue
    for (int l = 0; l < Ll; l++) {
        k_gemm_mma<<<dim3(MTILES, 2), 256>>>(l);
        k_agg_fused<<<Nn, 256>>>(convb + l * Hh, gamma + l * Hh, beta + l * Hh,
                                 mean + l * Hh, var + l * Hh);
    }

    // pooling + head
    k_pool<<<Gg, 256>>>(batch);
    k_sgemm<<<dim3(Hh / 64, Gg / 64), 256>>>(nullptr, W1, b1, Gg, Hh, 2 * Hh, 1, 2);
    k_sgemm<<<dim3((Hh / 2) / 64, Gg / 64), 256>>>(nullptr, W2, b2, Gg, Hh / 2, Hh, 1, 3);
    k_head3<<<(Gg * Tt + 255) / 256, 256>>>(W3, b3, out);
}

// round 6
// speedup vs baseline: 2.0558x; 1.4985x over previous
#include <cuda_runtime.h>
#include <cuda_bf16.h>
#include <math.h>
#include <float.h>
#include <stdint.h>

#define Nn   50000
#define FIN  64
#define Hh   256
#define Ee   800000
#define Gg   2048
#define Ll   4
#define Tt   4
#define EPSc 1e-5f

#define MTILES ((Nn + 127) / 128)   // 391
#define Mpad   (MTILES * 128)       // 50048

// ---------------- scratch ----------------
__device__ __align__(16) float g_h [Nn * Hh];
__device__ __align__(16) float g_hW[(size_t)Mpad * Hh];
__device__ float g_isd[Nn];
__device__ int   g_cnt[Nn];
__device__ int   g_off[Nn + 1];
__device__ int   g_cur[Nn];
__device__ int   g_csr[Ee];
__device__ float g_wgt[Ee];
__device__ int   g_part[64];
__device__ __align__(16) float g_pool[Gg * 2 * Hh];
__device__ __align__(16) float g_f1[Gg * Hh];
__device__ __align__(16) float g_f2[Gg * (Hh / 2)];
__device__ __align__(16) __nv_bfloat16 g_Ahi[(size_t)Mpad * Hh];
__device__ __align__(16) __nv_bfloat16 g_Alo[(size_t)Mpad * Hh];
__device__ __align__(16) __nv_bfloat16 g_Bhi[Ll * Hh * Hh];
__device__ __align__(16) __nv_bfloat16 g_Blo[Ll * Hh * Hh];

// ---------------- asm helpers ----------------
__device__ __forceinline__ uint32_t smem_u32(const void* p) {
    uint32_t a;
    asm("{ .reg .u64 t; cvta.to.shared.u64 t, %1; cvt.u32.u64 %0, t; }" : "=r"(a) : "l"(p));
    return a;
}
#define CPA(dst, src) \
    asm volatile("cp.async.cg.shared.global [%0], [%1], 16;" :: "r"(dst), "l"(src) : "memory")
#define LDSM4(r, addr) \
    asm volatile("ldmatrix.sync.aligned.m8n8.x4.shared.b16 {%0,%1,%2,%3}, [%4];" \
        : "=r"((r)[0]), "=r"((r)[1]), "=r"((r)[2]), "=r"((r)[3]) : "r"(addr))
#define LDSM4T(r, addr) \
    asm volatile("ldmatrix.sync.aligned.m8n8.x4.trans.shared.b16 {%0,%1,%2,%3}, [%4];" \
        : "=r"((r)[0]), "=r"((r)[1]), "=r"((r)[2]), "=r"((r)[3]) : "r"(addr))
#define MMA16816(c, a, b) \
    asm volatile("mma.sync.aligned.m16n8k16.row.col.f32.bf16.bf16.f32 " \
        "{%0,%1,%2,%3}, {%4,%5,%6,%7}, {%8,%9}, {%0,%1,%2,%3};" \
        : "+f"((c)[0]), "+f"((c)[1]), "+f"((c)[2]), "+f"((c)[3]) \
        : "r"((a)[0]), "r"((a)[1]), "r"((a)[2]), "r"((a)[3]), "r"((b)[0]), "r"((b)[1]))

// ---------------- degree / CSR ----------------
__global__ void k_zero_cnt() {
    int i = blockIdx.x * blockDim.x + threadIdx.x;
    if (i < Nn) g_cnt[i] = 0;
}
__global__ void k_count_edges(const int* __restrict__ ei) {
    int e = blockIdx.x * blockDim.x + threadIdx.x;
    if (e < Ee) atomicAdd(&g_cnt[ei[Ee + e]], 1);
}
__global__ void k_scan_block() {
    __shared__ int s[1024];
    int gid = blockIdx.x * 1024 + threadIdx.x;
    int v = (gid < Nn) ? g_cnt[gid] : 0;
    s[threadIdx.x] = v;
    for (int d = 1; d < 1024; d <<= 1) {
        __syncthreads();
        int t = (threadIdx.x >= d) ? s[threadIdx.x - d] : 0;
        __syncthreads();
        s[threadIdx.x] += t;
    }
    __syncthreads();
    if (gid < Nn) g_off[gid] = s[threadIdx.x] - v;
    if (threadIdx.x == 1023) g_part[blockIdx.x] = s[1023];
}
__global__ void k_scan_part(int nb) {
    if (threadIdx.x == 0 && blockIdx.x == 0) {
        int acc = 0;
        for (int i = 0; i < nb; i++) { int t = g_part[i]; g_part[i] = acc; acc += t; }
    }
}
__global__ void k_scan_add() {   // also computes isd
    int gid = blockIdx.x * 1024 + threadIdx.x;
    if (gid < Nn) {
        int v = g_off[gid] + g_part[blockIdx.x];
        g_off[gid] = v;
        g_cur[gid] = v;
        g_isd[gid] = rsqrtf(1.0f + (float)g_cnt[gid]);
    }
    if (gid == 0) g_off[Nn] = Ee;
}
__global__ void k_csr_fill(const int* __restrict__ ei) {   // also edge weights
    int e = blockIdx.x * blockDim.x + threadIdx.x;
    if (e < Ee) {
        int s = ei[e];
        int d = ei[Ee + e];
        int p = atomicAdd(&g_cur[d], 1);
        g_csr[p] = s;
        g_wgt[p] = g_isd[s] * g_isd[d];
    }
}

// ---------------- W split: [L][K][N] fp32 -> bf16 hi/lo ----------------
__global__ void k_convW(const float* __restrict__ convW) {
    int idx = blockIdx.x * blockDim.x + threadIdx.x;
    if (idx >= Ll * Hh * Hh) return;
    float w = convW[idx];
    __nv_bfloat16 hi = __float2bfloat16(w);
    g_Bhi[idx] = hi;
    g_Blo[idx] = __float2bfloat16(w - __bfloat162float(hi));
}

// ---------------- bf16x3 mma.sync GEMM, 3-slot cp.async ring ----------------
// CTA 128x128, K=256 in 8 stages of K32. One __syncthreads per stage.
// Slot layout (37888 B): A_hi[128x80B]=10240 | A_lo=10240 | B_hi[32x272B]=8704 | B_lo=8704
#define SLOT   37888
#define ALO_O  10240
#define BHI_O  20480
#define BLO_O  29184
#define SMEM_G (3 * SLOT)   // 113664

__global__ __launch_bounds__(256) void k_gemm_mma(int layer) {
    extern __shared__ __align__(16) unsigned char smraw[];
    const int tid = threadIdx.x, lane = tid & 31, wid = tid >> 5;
    const int warp_m = wid & 3, warp_n = wid >> 2;
    const int m0 = blockIdx.x * 128, n0 = blockIdx.y * 128;
    const uint32_t sb = smem_u32(smraw);

    const __nv_bfloat16* Bh = g_Bhi + (size_t)layer * Hh * Hh;
    const __nv_bfloat16* Bl = g_Blo + (size_t)layer * Hh * Hh;

    // per-thread cp.async slots (2 iterations each of A-hi/lo, B-hi/lo)
    const int a_r0 = tid >> 2, a_c0 = tid & 3;             // + it*256: row += 64
    const int b_r0 = tid >> 4, b_c0 = tid & 15;            // + it*256: row += 16

#define LOAD_STAGE(slotbase, kt) do { \
        int k0 = (kt) * 32; \
        _Pragma("unroll") \
        for (int it = 0; it < 2; it++) { \
            int ar = a_r0 + it * 64, ac = a_c0; \
            CPA((slotbase) + ar * 80 + ac * 16, \
                g_Ahi + (size_t)(m0 + ar) * Hh + k0 + ac * 8); \
            CPA((slotbase) + ALO_O + ar * 80 + ac * 16, \
                g_Alo + (size_t)(m0 + ar) * Hh + k0 + ac * 8); \
            int br = b_r0 + it * 16, bc = b_c0; \
            CPA((slotbase) + BHI_O + br * 272 + bc * 16, \
                Bh + (size_t)(k0 + br) * Hh + n0 + bc * 8); \
            CPA((slotbase) + BLO_O + br * 272 + bc * 16, \
                Bl + (size_t)(k0 + br) * Hh + n0 + bc * 8); \
        } \
        asm volatile("cp.async.commit_group;" ::: "memory"); \
    } while (0)

    float acc[2][8][4];
    #pragma unroll
    for (int i = 0; i < 2; i++)
        #pragma unroll
        for (int j = 0; j < 8; j++)
            #pragma unroll
            for (int q = 0; q < 4; q++) acc[i][j][q] = 0.f;

    const uint32_t aoff = sb + (warp_m * 32 + (lane & 15)) * 80 + (lane >> 4) * 16;
    const uint32_t boff = sb + BHI_O + (lane & 15) * 272 + (warp_n * 8 + (lane >> 4)) * 16;

    LOAD_STAGE(sb, 0);
    LOAD_STAGE(sb + SLOT, 1);

    #pragma unroll
    for (int kt = 0; kt < 8; kt++) {
        const uint32_t s = (kt % 3) * SLOT;
        asm volatile("cp.async.wait_group 1;" ::: "memory");
        __syncthreads();
        if (kt + 2 < 8) {
            LOAD_STAGE(sb + ((kt + 2) % 3) * SLOT, kt + 2);
        } else {
            asm volatile("cp.async.commit_group;" ::: "memory");
        }

        #pragma unroll
        for (int micro = 0; micro < 2; micro++) {
            uint32_t ah[2][4], al[2][4], bh[4][4], bl[4][4];
            #pragma unroll
            for (int mt = 0; mt < 2; mt++) {
                LDSM4(ah[mt], aoff + s + mt * 1280 + micro * 32);
                LDSM4(al[mt], aoff + s + ALO_O + mt * 1280 + micro * 32);
            }
            #pragma unroll
            for (int nt = 0; nt < 4; nt++) {
                LDSM4T(bh[nt], boff + s + nt * 32 + micro * 4352);
                LDSM4T(bl[nt], boff + s + 8704 + nt * 32 + micro * 4352);
            }
            #pragma unroll
            for (int mt = 0; mt < 2; mt++)
                #pragma unroll
                for (int nt = 0; nt < 4; nt++)
                    #pragma unroll
                    for (int nb = 0; nb < 2; nb++) {
                        float* c = acc[mt][nt * 2 + nb];
                        MMA16816(c, ah[mt], &bh[nt][nb * 2]);
                        MMA16816(c, ah[mt], &bl[nt][nb * 2]);
                        MMA16816(c, al[mt], &bh[nt][nb * 2]);
                    }
        }
    }
#undef LOAD_STAGE

    #pragma unroll
    for (int mt = 0; mt < 2; mt++) {
        int r0 = m0 + warp_m * 32 + mt * 16 + (lane >> 2);
        #pragma unroll
        for (int j = 0; j < 8; j++) {
            int n = n0 + warp_n * 64 + j * 8 + (lane & 3) * 2;
            float2 v0 = {acc[mt][j][0], acc[mt][j][1]};
            float2 v1 = {acc[mt][j][2], acc[mt][j][3]};
            *(float2*)&g_hW[(size_t)r0 * Hh + n] = v0;
            *(float2*)&g_hW[(size_t)(r0 + 8) * Hh + n] = v1;
        }
    }
}

// ---------------- SIMT SGEMM (proj + head) ----------------
__global__ void k_sgemm(const float* __restrict__ Aext, const float* __restrict__ B,
                        const float* __restrict__ bias,
                        int M, int N, int K, int doRelu, int sel) {
    const float* A = (sel == 0) ? Aext : (sel == 2) ? g_pool : g_f1;
    float*       C = (sel == 0) ? g_h  : (sel == 2) ? g_f1  : g_f2;

    __shared__ float As[16][64];
    __shared__ float Bs[16][68];

    int tid = threadIdx.x;
    int m0 = blockIdx.y * 64, n0 = blockIdx.x * 64;
    int tr = tid >> 4, tc = tid & 15;
    int arow = tid >> 2, aq = (tid & 3) * 4;
    int brow = tid >> 4, bq = (tid & 15) * 4;

    float acc[4][4];
    #pragma unroll
    for (int i = 0; i < 4; i++)
        #pragma unroll
        for (int j = 0; j < 4; j++) acc[i][j] = 0.f;

    for (int k0 = 0; k0 < K; k0 += 16) {
        float4 av;
        if (m0 + arow < M)
            av = *reinterpret_cast<const float4*>(&A[(size_t)(m0 + arow) * K + k0 + aq]);
        else
            av = make_float4(0.f, 0.f, 0.f, 0.f);
        As[aq + 0][arow] = av.x;
        As[aq + 1][arow] = av.y;
        As[aq + 2][arow] = av.z;
        As[aq + 3][arow] = av.w;

        float4 bv = *reinterpret_cast<const float4*>(&B[(size_t)(k0 + brow) * N + n0 + bq]);
        Bs[brow][bq + 0] = bv.x;
        Bs[brow][bq + 1] = bv.y;
        Bs[brow][bq + 2] = bv.z;
        Bs[brow][bq + 3] = bv.w;
        __syncthreads();

        #pragma unroll
        for (int k = 0; k < 16; k++) {
            float arr[4], br[4];
            #pragma unroll
            for (int i = 0; i < 4; i++) arr[i] = As[k][tr * 4 + i];
            #pragma unroll
            for (int j = 0; j < 4; j++) br[j] = Bs[k][tc * 4 + j];
            #pragma unroll
            for (int i = 0; i < 4; i++)
                #pragma unroll
                for (int j = 0; j < 4; j++) acc[i][j] = fmaf(arr[i], br[j], acc[i][j]);
        }
        __syncthreads();
    }

    #pragma unroll
    for (int i = 0; i < 4; i++) {
        int m = m0 + tr * 4 + i;
        if (m >= M) continue;
        #pragma unroll
        for (int j = 0; j < 4; j++) {
            int n = n0 + tc * 4 + j;
            float v = acc[i][j];
            if (bias) v += bias[n];
            if (doRelu) v = fmaxf(v, 0.f);
            C[(size_t)m * N + n] = v;
            if (sel == 0) {
                __nv_bfloat16 hi = __float2bfloat16(v);
                g_Ahi[(size_t)m * Hh + n] = hi;
                g_Alo[(size_t)m * Hh + n] = __float2bfloat16(v - __bfloat162float(hi));
            }
        }
    }
}

// ---------------- fused aggregation + bias + BN + ReLU + residual + bf16 split ----------------
// 4 nodes per 256-thread block; 64 threads x float4 per node; edge loop unrolled x4
__global__ __launch_bounds__(256) void k_agg_fused(
        const float* __restrict__ bias, const float* __restrict__ gamma,
        const float* __restrict__ beta, const float* __restrict__ mean,
        const float* __restrict__ var) {
    int v = blockIdx.x * 4 + (threadIdx.x >> 6);
    if (v >= Nn) return;
    int c = (threadIdx.x & 63) * 4;

    float idv = g_isd[v];
    float ws = idv * idv;
    float4 acc = *(const float4*)&g_hW[(size_t)v * Hh + c];
    acc.x *= ws; acc.y *= ws; acc.z *= ws; acc.w *= ws;

    int j = g_off[v], e = g_off[v + 1];
    for (; j + 4 <= e; j += 4) {
        int u0 = g_csr[j], u1 = g_csr[j + 1], u2 = g_csr[j + 2], u3 = g_csr[j + 3];
        float w0 = g_wgt[j], w1 = g_wgt[j + 1], w2 = g_wgt[j + 2], w3 = g_wgt[j + 3];
        float4 r0 = *(const float4*)&g_hW[(size_t)u0 * Hh + c];
        float4 r1 = *(const float4*)&g_hW[(size_t)u1 * Hh + c];
        float4 r2 = *(const float4*)&g_hW[(size_t)u2 * Hh + c];
        float4 r3 = *(const float4*)&g_hW[(size_t)u3 * Hh + c];
        acc.x = fmaf(r0.x, w0, fmaf(r1.x, w1, fmaf(r2.x, w2, fmaf(r3.x, w3, acc.x))));
        acc.y = fmaf(r0.y, w0, fmaf(r1.y, w1, fmaf(r2.y, w2, fmaf(r3.y, w3, acc.y))));
        acc.z = fmaf(r0.z, w0, fmaf(r1.z, w1, fmaf(r2.z, w2, fmaf(r3.z, w3, acc.z))));
        acc.w = fmaf(r0.w, w0, fmaf(r1.w, w1, fmaf(r2.w, w2, fmaf(r3.w, w3, acc.w))));
    }
    for (; j < e; j++) {
        int u = g_csr[j];
        float w = g_wgt[j];
        float4 r = *(const float4*)&g_hW[(size_t)u * Hh + c];
        acc.x = fmaf(r.x, w, acc.x);
        acc.y = fmaf(r.y, w, acc.y);
        acc.z = fmaf(r.z, w, acc.z);
        acc.w = fmaf(r.w, w, acc.w);
    }

    float4 bi = *(const float4*)&bias[c];
    float4 ga = *(const float4*)&gamma[c];
    float4 be = *(const float4*)&beta[c];
    float4 me = *(const float4*)&mean[c];
    float4 va = *(const float4*)&var[c];
    float4 res = *(const float4*)&g_h[(size_t)v * Hh + c];

    float4 o;
    o.x = fmaxf((acc.x + bi.x - me.x) * (ga.x * rsqrtf(va.x + EPSc)) + be.x, 0.f) + res.x;
    o.y = fmaxf((acc.y + bi.y - me.y) * (ga.y * rsqrtf(va.y + EPSc)) + be.y, 0.f) + res.y;
    o.z = fmaxf((acc.z + bi.z - me.z) * (ga.z * rsqrtf(va.z + EPSc)) + be.z, 0.f) + res.z;
    o.w = fmaxf((acc.w + bi.w - me.w) * (ga.w * rsqrtf(va.w + EPSc)) + be.w, 0.f) + res.w;
    *(float4*)&g_h[(size_t)v * Hh + c] = o;

    __nv_bfloat16 h0 = __float2bfloat16(o.x), h1 = __float2bfloat16(o.y);
    __nv_bfloat16 h2 = __float2bfloat16(o.z), h3 = __float2bfloat16(o.w);
    uint2 hv, lv;
    hv.x = ((uint32_t)*(uint16_t*)&h1 << 16) | *(uint16_t*)&h0;
    hv.y = ((uint32_t)*(uint16_t*)&h3 << 16) | *(uint16_t*)&h2;
    __nv_bfloat16 l0 = __float2bfloat16(o.x - __bfloat162float(h0));
    __nv_bfloat16 l1 = __float2bfloat16(o.y - __bfloat162float(h1));
    __nv_bfloat16 l2 = __float2bfloat16(o.z - __bfloat162float(h2));
    __nv_bfloat16 l3 = __float2bfloat16(o.w - __bfloat162float(h3));
    lv.x = ((uint32_t)*(uint16_t*)&l1 << 16) | *(uint16_t*)&l0;
    lv.y = ((uint32_t)*(uint16_t*)&l3 << 16) | *(uint16_t*)&l2;
    *(uint2*)&g_Ahi[(size_t)v * Hh + c] = hv;
    *(uint2*)&g_Alo[(size_t)v * Hh + c] = lv;
}

// ---------------- pooling ----------------
__global__ void k_pool(const int* __restrict__ batch) {
    __shared__ int sbb[2];
    int grp = blockIdx.x, t = threadIdx.x;
    if (t < 2) {
        int key = grp + t;
        int lo = 0, hi = Nn;
        while (lo < hi) {
            int mid = (lo + hi) >> 1;
            if (batch[mid] < key) lo = mid + 1; else hi = mid;
        }
        sbb[t] = lo;
    }
    __syncthreads();
    int s = sbb[0], e = sbb[1];
    float sum = 0.f, mx = -FLT_MAX;
    for (int i = s; i < e; i++) {
        float v = g_h[(size_t)i * Hh + t];
        sum += v;
        mx = fmaxf(mx, v);
    }
    float c = (float)(e - s);
    g_pool[(size_t)grp * (2 * Hh) + t]      = sum / fmaxf(c, 1.f);
    g_pool[(size_t)grp * (2 * Hh) + Hh + t] = mx;
}

// ---------------- final tiny GEMM ----------------
__global__ void k_head3(const float* __restrict__ W, const float* __restrict__ b,
                        float* __restrict__ out) {
    int idx = blockIdx.x * blockDim.x + threadIdx.x;
    if (idx >= Gg * Tt) return;
    int r = idx >> 2, c = idx & 3;
    float acc = b[c];
    const float* row = &g_f2[(size_t)r * 128];
    #pragma unroll 8
    for (int k = 0; k < 128; k++) acc = fmaf(row[k], W[k * 4 + c], acc);
    out[idx] = acc;
}

// ---------------- launch ----------------
extern "C" void kernel_launch(void* const* d_in, const int* in_sizes, int n_in,
                              void* d_out, int out_size) {
    const float* x     = (const float*)d_in[0];
    const int*   ei    = (const int*)d_in[1];
    const int*   batch = (const int*)d_in[2];
    const float* projW = (const float*)d_in[3];
    const float* projb = (const float*)d_in[4];
    const float* convW = (const float*)d_in[5];
    const float* convb = (const float*)d_in[6];
    const float* gamma = (const float*)d_in[7];
    const float* beta  = (const float*)d_in[8];
    const float* mean  = (const float*)d_in[9];
    const float* var   = (const float*)d_in[10];
    const float* W1 = (const float*)d_in[11];
    const float* b1 = (const float*)d_in[12];
    const float* W2 = (const float*)d_in[13];
    const float* b2 = (const float*)d_in[14];
    const float* W3 = (const float*)d_in[15];
    const float* b3 = (const float*)d_in[16];
    float* out = (float*)d_out;

    const int SCAN_B = (Nn + 1023) / 1024;

    cudaFuncSetAttribute(k_gemm_mma, cudaFuncAttributeMaxDynamicSharedMemorySize, SMEM_G);

    // CSR + degree norm + weight split
    k_zero_cnt   <<<(Nn + 255) / 256, 256>>>();
    k_count_edges<<<(Ee + 255) / 256, 256>>>(ei);
    k_scan_block <<<SCAN_B, 1024>>>();
    k_scan_part  <<<1, 32>>>(SCAN_B);
    k_scan_add   <<<SCAN_B, 1024>>>();
    k_csr_fill   <<<(Ee + 255) / 256, 256>>>(ei);
    k_convW      <<<(Ll * Hh * Hh + 255) / 256, 256>>>(convW);

    // projection (emits g_h + bf16 split)
    k_sgemm<<<dim3(Hh / 64, (Nn + 63) / 64), 256>>>(x, projW, projb, Nn, Hh, FIN, 1, 0);

    // 4 GCN layers
    for (int l = 0; l < Ll; l++) {
        k_gemm_mma<<<dim3(MTILES, 2), 256, SMEM_G>>>(l);
        k_agg_fused<<<(Nn + 3) / 4, 256>>>(convb + l * Hh, gamma + l * Hh, beta + l * Hh,
                                           mean + l * Hh, var + l * Hh);
    }

    // pooling + head
    k_pool<<<Gg, 256>>>(batch);
    k_sgemm<<<dim3(Hh / 64, Gg / 64), 256>>>(nullptr, W1, b1, Gg, Hh, 2 * Hh, 1, 2);
    k_sgemm<<<dim3((Hh / 2) / 64, Gg / 64), 256>>>(nullptr, W2, b2, Gg, Hh / 2, Hh, 1, 3);
    k_head3<<<(Gg * Tt + 255) / 256, 256>>>(W3, b3, out);
}

// round 7
// speedup vs baseline: 2.1669x; 1.0540x over previous
#include <cuda_runtime.h>
#include <cuda_bf16.h>
#include <math.h>
#include <float.h>
#include <stdint.h>

#define Nn   50000
#define FIN  64
#define Hh   256
#define Ee   800000
#define Gg   2048
#define Ll   4
#define Tt   4
#define EPSc 1e-5f

#define MTILES ((Nn + 127) / 128)   // 391
#define Mpad   (MTILES * 128)       // 50048

// ---------------- scratch ----------------
__device__ __align__(16) float g_h [Nn * Hh];
__device__ __align__(16) float g_hW[(size_t)Mpad * Hh];
__device__ float g_isd[Nn];
__device__ int   g_cnt[Nn];
__device__ int   g_off[Nn + 1];
__device__ int   g_cur[Nn];
__device__ int   g_csr[Ee];
__device__ float g_wgt[Ee];
__device__ int   g_part[64];
__device__ __align__(16) float g_pool[Gg * 2 * Hh];
__device__ __align__(16) float g_f1[Gg * Hh];
__device__ __align__(16) float g_f2[Gg * (Hh / 2)];
__device__ __align__(16) __nv_bfloat16 g_Ahi[(size_t)Mpad * Hh];
__device__ __align__(16) __nv_bfloat16 g_Alo[(size_t)Mpad * Hh];
__device__ __align__(16) __nv_bfloat16 g_Bhi[Ll * Hh * Hh];
__device__ __align__(16) __nv_bfloat16 g_Blo[Ll * Hh * Hh];
__device__ __align__(16) __nv_bfloat16 g_Xhi[(size_t)Mpad * FIN];
__device__ __align__(16) __nv_bfloat16 g_Xlo[(size_t)Mpad * FIN];
__device__ __align__(16) __nv_bfloat16 g_PBhi[FIN * Hh];
__device__ __align__(16) __nv_bfloat16 g_PBlo[FIN * Hh];

// ---------------- asm helpers ----------------
__device__ __forceinline__ uint32_t smem_u32(const void* p) {
    uint32_t a;
    asm("{ .reg .u64 t; cvta.to.shared.u64 t, %1; cvt.u32.u64 %0, t; }" : "=r"(a) : "l"(p));
    return a;
}
#define CPA(dst, src) \
    asm volatile("cp.async.cg.shared.global [%0], [%1], 16;" :: "r"(dst), "l"(src) : "memory")
#define LDSM4(r, addr) \
    asm volatile("ldmatrix.sync.aligned.m8n8.x4.shared.b16 {%0,%1,%2,%3}, [%4];" \
        : "=r"((r)[0]), "=r"((r)[1]), "=r"((r)[2]), "=r"((r)[3]) : "r"(addr))
#define LDSM4T(r, addr) \
    asm volatile("ldmatrix.sync.aligned.m8n8.x4.trans.shared.b16 {%0,%1,%2,%3}, [%4];" \
        : "=r"((r)[0]), "=r"((r)[1]), "=r"((r)[2]), "=r"((r)[3]) : "r"(addr))
#define MMA16816(c, a, b) \
    asm volatile("mma.sync.aligned.m16n8k16.row.col.f32.bf16.bf16.f32 " \
        "{%0,%1,%2,%3}, {%4,%5,%6,%7}, {%8,%9}, {%0,%1,%2,%3};" \
        : "+f"((c)[0]), "+f"((c)[1]), "+f"((c)[2]), "+f"((c)[3]) \
        : "r"((a)[0]), "r"((a)[1]), "r"((a)[2]), "r"((a)[3]), "r"((b)[0]), "r"((b)[1]))

__device__ __forceinline__ uint32_t pack_hi2(float x, float y) {
    __nv_bfloat16 a = __float2bfloat16(x), b = __float2bfloat16(y);
    return ((uint32_t)*(uint16_t*)&b << 16) | *(uint16_t*)&a;
}
__device__ __forceinline__ uint32_t pack_lo2(float x, float y) {
    __nv_bfloat16 a = __float2bfloat16(x), b = __float2bfloat16(y);
    __nv_bfloat16 la = __float2bfloat16(x - __bfloat162float(a));
    __nv_bfloat16 lb = __float2bfloat16(y - __bfloat162float(b));
    return ((uint32_t)*(uint16_t*)&lb << 16) | *(uint16_t*)&la;
}

// ---------------- setup kernels ----------------
__global__ void k_zero_cnt() {
    int i = blockIdx.x * blockDim.x + threadIdx.x;
    if (i < Nn) g_cnt[i] = 0;
}
// x [Nn,64] fp32 -> bf16 hi/lo
__global__ void k_split_x(const float* __restrict__ x) {
    int idx = blockIdx.x * blockDim.x + threadIdx.x;     // one float4
    if (idx >= Nn * FIN / 4) return;
    float4 v = *(const float4*)&x[idx * 4];
    uint2 hv, lv;
    hv.x = pack_hi2(v.x, v.y); hv.y = pack_hi2(v.z, v.w);
    lv.x = pack_lo2(v.x, v.y); lv.y = pack_lo2(v.z, v.w);
    *(uint2*)&g_Xhi[idx * 4] = hv;
    *(uint2*)&g_Xlo[idx * 4] = lv;
}
// convW [L,H,H] + projW [64,H] -> bf16 hi/lo
__global__ void k_wsplit(const float* __restrict__ convW, const float* __restrict__ projW) {
    int idx = blockIdx.x * blockDim.x + threadIdx.x;
    if (idx < Ll * Hh * Hh) {
        float w = convW[idx];
        __nv_bfloat16 hi = __float2bfloat16(w);
        g_Bhi[idx] = hi;
        g_Blo[idx] = __float2bfloat16(w - __bfloat162float(hi));
    } else if (idx < Ll * Hh * Hh + FIN * Hh) {
        int j = idx - Ll * Hh * Hh;
        float w = projW[j];
        __nv_bfloat16 hi = __float2bfloat16(w);
        g_PBhi[j] = hi;
        g_PBlo[j] = __float2bfloat16(w - __bfloat162float(hi));
    }
}
__global__ void k_count_edges(const int* __restrict__ ei) {
    int e = blockIdx.x * blockDim.x + threadIdx.x;
    if (e < Ee) atomicAdd(&g_cnt[ei[Ee + e]], 1);
}
__global__ void k_scan_block() {
    __shared__ int s[1024];
    int gid = blockIdx.x * 1024 + threadIdx.x;
    int v = (gid < Nn) ? g_cnt[gid] : 0;
    s[threadIdx.x] = v;
    for (int d = 1; d < 1024; d <<= 1) {
        __syncthreads();
        int t = (threadIdx.x >= d) ? s[threadIdx.x - d] : 0;
        __syncthreads();
        s[threadIdx.x] += t;
    }
    __syncthreads();
    if (gid < Nn) g_off[gid] = s[threadIdx.x] - v;
    if (threadIdx.x == 1023) g_part[blockIdx.x] = s[1023];
}
// adds preceding partials (summed locally), finalizes cur + isd
__global__ void k_scan_add() {
    __shared__ int base;
    if (threadIdx.x == 0) {
        int acc = 0;
        for (int i = 0; i < blockIdx.x; i++) acc += g_part[i];
        base = acc;
    }
    __syncthreads();
    int gid = blockIdx.x * 1024 + threadIdx.x;
    if (gid < Nn) {
        int v = g_off[gid] + base;
        g_off[gid] = v;
        g_cur[gid] = v;
        g_isd[gid] = rsqrtf(1.0f + (float)g_cnt[gid]);
    }
    if (gid == 0) g_off[Nn] = Ee;
}
__global__ void k_csr_fill(const int* __restrict__ ei) {
    int e = blockIdx.x * blockDim.x + threadIdx.x;
    if (e < Ee) {
        int s = ei[e];
        int d = ei[Ee + e];
        int p = atomicAdd(&g_cur[d], 1);
        g_csr[p] = s;
        g_wgt[p] = g_isd[s] * g_isd[d];
    }
}

// ---------------- bf16x3 mma.sync GEMM, 3-slot cp.async ring ----------------
// MODE 0 (conv): A = g_Ahi/g_Alo [Mpad,256], B = g_Bhi/g_Blo + layer, C = g_hW
// MODE 1 (proj): A = g_Xhi/g_Xlo [Mpad,64],  B = g_PBhi/g_PBlo, C = relu(.+bias) -> g_h + split
#define SLOT   37888
#define ALO_O  10240
#define BHI_O  20480
#define BLO_O  29184
#define SMEM_G (3 * SLOT)   // 113664

template<int KSTAGES, int MODE>
__global__ __launch_bounds__(256) void k_gemm_mma(int layer, const float* __restrict__ bias) {
    extern __shared__ __align__(16) unsigned char smraw[];
    const int tid = threadIdx.x, lane = tid & 31, wid = tid >> 5;
    const int warp_m = wid & 3, warp_n = wid >> 2;
    const int m0 = blockIdx.x * 128, n0 = blockIdx.y * 128;
    const uint32_t sb = smem_u32(smraw);
    const int kdim = KSTAGES * 32;

    const __nv_bfloat16* Ah = (MODE == 0) ? g_Ahi : g_Xhi;
    const __nv_bfloat16* Al = (MODE == 0) ? g_Alo : g_Xlo;
    const __nv_bfloat16* Bh = (MODE == 0) ? g_Bhi + (size_t)layer * Hh * Hh : g_PBhi;
    const __nv_bfloat16* Bl = (MODE == 0) ? g_Blo + (size_t)layer * Hh * Hh : g_PBlo;

    const int a_r0 = tid >> 2, a_c0 = tid & 3;
    const int b_r0 = tid >> 4, b_c0 = tid & 15;

#define LOAD_STAGE(slotbase, kt) do { \
        int k0 = (kt) * 32; \
        _Pragma("unroll") \
        for (int it = 0; it < 2; it++) { \
            int ar = a_r0 + it * 64, ac = a_c0; \
            CPA((slotbase) + ar * 80 + ac * 16, \
                Ah + (size_t)(m0 + ar) * kdim + k0 + ac * 8); \
            CPA((slotbase) + ALO_O + ar * 80 + ac * 16, \
                Al + (size_t)(m0 + ar) * kdim + k0 + ac * 8); \
            int br = b_r0 + it * 16, bc = b_c0; \
            CPA((slotbase) + BHI_O + br * 272 + bc * 16, \
                Bh + (size_t)(k0 + br) * Hh + n0 + bc * 8); \
            CPA((slotbase) + BLO_O + br * 272 + bc * 16, \
                Bl + (size_t)(k0 + br) * Hh + n0 + bc * 8); \
        } \
        asm volatile("cp.async.commit_group;" ::: "memory"); \
    } while (0)

    float acc[2][8][4];
    #pragma unroll
    for (int i = 0; i < 2; i++)
        #pragma unroll
        for (int j = 0; j < 8; j++)
            #pragma unroll
            for (int q = 0; q < 4; q++) acc[i][j][q] = 0.f;

    const uint32_t aoff = sb + (warp_m * 32 + (lane & 15)) * 80 + (lane >> 4) * 16;
    const uint32_t boff = sb + BHI_O + (lane & 15) * 272 + (warp_n * 8 + (lane >> 4)) * 16;

    LOAD_STAGE(sb, 0);
    LOAD_STAGE(sb + SLOT, 1);

    #pragma unroll
    for (int kt = 0; kt < KSTAGES; kt++) {
        const uint32_t s = (kt % 3) * SLOT;
        asm volatile("cp.async.wait_group 1;" ::: "memory");
        __syncthreads();
        if (kt + 2 < KSTAGES) {
            LOAD_STAGE(sb + ((kt + 2) % 3) * SLOT, kt + 2);
        } else {
            asm volatile("cp.async.commit_group;" ::: "memory");
        }

        #pragma unroll
        for (int micro = 0; micro < 2; micro++) {
            uint32_t ah[2][4], al[2][4], bh[4][4], bl[4][4];
            #pragma unroll
            for (int mt = 0; mt < 2; mt++) {
                LDSM4(ah[mt], aoff + s + mt * 1280 + micro * 32);
                LDSM4(al[mt], aoff + s + ALO_O + mt * 1280 + micro * 32);
            }
            #pragma unroll
            for (int nt = 0; nt < 4; nt++) {
                LDSM4T(bh[nt], boff + s + nt * 32 + micro * 4352);
                LDSM4T(bl[nt], boff + s + 8704 + nt * 32 + micro * 4352);
            }
            #pragma unroll
            for (int mt = 0; mt < 2; mt++)
                #pragma unroll
                for (int nt = 0; nt < 4; nt++)
                    #pragma unroll
                    for (int nb = 0; nb < 2; nb++) {
                        float* c = acc[mt][nt * 2 + nb];
                        MMA16816(c, ah[mt], &bh[nt][nb * 2]);
                        MMA16816(c, ah[mt], &bl[nt][nb * 2]);
                        MMA16816(c, al[mt], &bh[nt][nb * 2]);
                    }
        }
    }
#undef LOAD_STAGE

    #pragma unroll
    for (int mt = 0; mt < 2; mt++) {
        int rbase = m0 + warp_m * 32 + mt * 16 + (lane >> 2);
        #pragma unroll
        for (int half = 0; half < 2; half++) {
            int r = rbase + half * 8;
            #pragma unroll
            for (int j = 0; j < 8; j++) {
                int n = n0 + warp_n * 64 + j * 8 + (lane & 3) * 2;
                float vx = acc[mt][j][half * 2 + 0];
                float vy = acc[mt][j][half * 2 + 1];
                if (MODE == 0) {
                    float2 v = {vx, vy};
                    *(float2*)&g_hW[(size_t)r * Hh + n] = v;
                } else if (r < Nn) {
                    float2 bi = *(const float2*)&bias[n];
                    vx = fmaxf(vx + bi.x, 0.f);
                    vy = fmaxf(vy + bi.y, 0.f);
                    float2 v = {vx, vy};
                    *(float2*)&g_h[(size_t)r * Hh + n] = v;
                    *(uint32_t*)&g_Ahi[(size_t)r * Hh + n] = pack_hi2(vx, vy);
                    *(uint32_t*)&g_Alo[(size_t)r * Hh + n] = pack_lo2(vx, vy);
                }
            }
        }
    }
}

// ---------------- SIMT SGEMM (head only) ----------------
//   sel 2: A = g_pool, C = g_f1 ; sel 3: A = g_f1, C = g_f2
__global__ void k_sgemm(const float* __restrict__ B, const float* __restrict__ bias,
                        int M, int N, int K, int sel) {
    const float* A = (sel == 2) ? g_pool : g_f1;
    float*       C = (sel == 2) ? g_f1  : g_f2;

    __shared__ float As[16][64];
    __shared__ float Bs[16][68];

    int tid = threadIdx.x;
    int m0 = blockIdx.y * 64, n0 = blockIdx.x * 64;
    int tr = tid >> 4, tc = tid & 15;
    int arow = tid >> 2, aq = (tid & 3) * 4;
    int brow = tid >> 4, bq = (tid & 15) * 4;

    float acc[4][4];
    #pragma unroll
    for (int i = 0; i < 4; i++)
        #pragma unroll
        for (int j = 0; j < 4; j++) acc[i][j] = 0.f;

    for (int k0 = 0; k0 < K; k0 += 16) {
        float4 av;
        if (m0 + arow < M)
            av = *reinterpret_cast<const float4*>(&A[(size_t)(m0 + arow) * K + k0 + aq]);
        else
            av = make_float4(0.f, 0.f, 0.f, 0.f);
        As[aq + 0][arow] = av.x;
        As[aq + 1][arow] = av.y;
        As[aq + 2][arow] = av.z;
        As[aq + 3][arow] = av.w;

        float4 bv = *reinterpret_cast<const float4*>(&B[(size_t)(k0 + brow) * N + n0 + bq]);
        Bs[brow][bq + 0] = bv.x;
        Bs[brow][bq + 1] = bv.y;
        Bs[brow][bq + 2] = bv.z;
        Bs[brow][bq + 3] = bv.w;
        __syncthreads();

        #pragma unroll
        for (int k = 0; k < 16; k++) {
            float arr[4], br[4];
            #pragma unroll
            for (int i = 0; i < 4; i++) arr[i] = As[k][tr * 4 + i];
            #pragma unroll
            for (int j = 0; j < 4; j++) br[j] = Bs[k][tc * 4 + j];
            #pragma unroll
            for (int i = 0; i < 4; i++)
                #pragma unroll
                for (int j = 0; j < 4; j++) acc[i][j] = fmaf(arr[i], br[j], acc[i][j]);
        }
        __syncthreads();
    }

    #pragma unroll
    for (int i = 0; i < 4; i++) {
        int m = m0 + tr * 4 + i;
        if (m >= M) continue;
        #pragma unroll
        for (int j = 0; j < 4; j++) {
            int n = n0 + tc * 4 + j;
            float v = fmaxf(acc[i][j] + bias[n], 0.f);
            C[(size_t)m * N + n] = v;
        }
    }
}

// ---------------- fused aggregation + bias + BN + ReLU + residual + bf16 split ----------------
__global__ __launch_bounds__(256) void k_agg_fused(
        const float* __restrict__ bias, const float* __restrict__ gamma,
        const float* __restrict__ beta, const float* __restrict__ mean,
        const float* __restrict__ var) {
    int v = blockIdx.x * 4 + (threadIdx.x >> 6);
    if (v >= Nn) return;
    int c = (threadIdx.x & 63) * 4;

    float idv = g_isd[v];
    float ws = idv * idv;
    float4 acc = *(const float4*)&g_hW[(size_t)v * Hh + c];
    acc.x *= ws; acc.y *= ws; acc.z *= ws; acc.w *= ws;

    int j = g_off[v], e = g_off[v + 1];
    for (; j + 4 <= e; j += 4) {
        int u0 = g_csr[j], u1 = g_csr[j + 1], u2 = g_csr[j + 2], u3 = g_csr[j + 3];
        float w0 = g_wgt[j], w1 = g_wgt[j + 1], w2 = g_wgt[j + 2], w3 = g_wgt[j + 3];
        float4 r0 = *(const float4*)&g_hW[(size_t)u0 * Hh + c];
        float4 r1 = *(const float4*)&g_hW[(size_t)u1 * Hh + c];
        float4 r2 = *(const float4*)&g_hW[(size_t)u2 * Hh + c];
        float4 r3 = *(const float4*)&g_hW[(size_t)u3 * Hh + c];
        acc.x = fmaf(r0.x, w0, fmaf(r1.x, w1, fmaf(r2.x, w2, fmaf(r3.x, w3, acc.x))));
        acc.y = fmaf(r0.y, w0, fmaf(r1.y, w1, fmaf(r2.y, w2, fmaf(r3.y, w3, acc.y))));
        acc.z = fmaf(r0.z, w0, fmaf(r1.z, w1, fmaf(r2.z, w2, fmaf(r3.z, w3, acc.z))));
        acc.w = fmaf(r0.w, w0, fmaf(r1.w, w1, fmaf(r2.w, w2, fmaf(r3.w, w3, acc.w))));
    }
    for (; j < e; j++) {
        int u = g_csr[j];
        float w = g_wgt[j];
        float4 r = *(const float4*)&g_hW[(size_t)u * Hh + c];
        acc.x = fmaf(r.x, w, acc.x);
        acc.y = fmaf(r.y, w, acc.y);
        acc.z = fmaf(r.z, w, acc.z);
        acc.w = fmaf(r.w, w, acc.w);
    }

    float4 bi = *(const float4*)&bias[c];
    float4 ga = *(const float4*)&gamma[c];
    float4 be = *(const float4*)&beta[c];
    float4 me = *(const float4*)&mean[c];
    float4 va = *(const float4*)&var[c];
    float4 res = *(const float4*)&g_h[(size_t)v * Hh + c];

    float4 o;
    o.x = fmaxf((acc.x + bi.x - me.x) * (ga.x * rsqrtf(va.x + EPSc)) + be.x, 0.f) + res.x;
    o.y = fmaxf((acc.y + bi.y - me.y) * (ga.y * rsqrtf(va.y + EPSc)) + be.y, 0.f) + res.y;
    o.z = fmaxf((acc.z + bi.z - me.z) * (ga.z * rsqrtf(va.z + EPSc)) + be.z, 0.f) + res.z;
    o.w = fmaxf((acc.w + bi.w - me.w) * (ga.w * rsqrtf(va.w + EPSc)) + be.w, 0.f) + res.w;
    *(float4*)&g_h[(size_t)v * Hh + c] = o;

    uint2 hv, lv;
    hv.x = pack_hi2(o.x, o.y); hv.y = pack_hi2(o.z, o.w);
    lv.x = pack_lo2(o.x, o.y); lv.y = pack_lo2(o.z, o.w);
    *(uint2*)&g_Ahi[(size_t)v * Hh + c] = hv;
    *(uint2*)&g_Alo[(size_t)v * Hh + c] = lv;
}

// ---------------- pooling ----------------
__global__ void k_pool(const int* __restrict__ batch) {
    __shared__ int sbb[2];
    int grp = blockIdx.x, t = threadIdx.x;
    if (t < 2) {
        int key = grp + t;
        int lo = 0, hi = Nn;
        while (lo < hi) {
            int mid = (lo + hi) >> 1;
            if (batch[mid] < key) lo = mid + 1; else hi = mid;
        }
        sbb[t] = lo;
    }
    __syncthreads();
    int s = sbb[0], e = sbb[1];
    float sum = 0.f, mx = -FLT_MAX;
    for (int i = s; i < e; i++) {
        float v = g_h[(size_t)i * Hh + t];
        sum += v;
        mx = fmaxf(mx, v);
    }
    float c = (float)(e - s);
    g_pool[(size_t)grp * (2 * Hh) + t]      = sum / fmaxf(c, 1.f);
    g_pool[(size_t)grp * (2 * Hh) + Hh + t] = mx;
}

// ---------------- final tiny GEMM ----------------
__global__ void k_head3(const float* __restrict__ W, const float* __restrict__ b,
                        float* __restrict__ out) {
    int idx = blockIdx.x * blockDim.x + threadIdx.x;
    if (idx >= Gg * Tt) return;
    int r = idx >> 2, c = idx & 3;
    float acc = b[c];
    const float* row = &g_f2[(size_t)r * 128];
    #pragma unroll 8
    for (int k = 0; k < 128; k++) acc = fmaf(row[k], W[k * 4 + c], acc);
    out[idx] = acc;
}

// ---------------- launch ----------------
extern "C" void kernel_launch(void* const* d_in, const int* in_sizes, int n_in,
                              void* d_out, int out_size) {
    const float* x     = (const float*)d_in[0];
    const int*   ei    = (const int*)d_in[1];
    const int*   batch = (const int*)d_in[2];
    const float* projW = (const float*)d_in[3];
    const float* projb = (const float*)d_in[4];
    const float* convW = (const float*)d_in[5];
    const float* convb = (const float*)d_in[6];
    const float* gamma = (const float*)d_in[7];
    const float* beta  = (const float*)d_in[8];
    const float* mean  = (const float*)d_in[9];
    const float* var   = (const float*)d_in[10];
    const float* W1 = (const float*)d_in[11];
    const float* b1 = (const float*)d_in[12];
    const float* W2 = (const float*)d_in[13];
    const float* b2 = (const float*)d_in[14];
    const float* W3 = (const float*)d_in[15];
    const float* b3 = (const float*)d_in[16];
    float* out = (float*)d_out;

    const int SCAN_B = (Nn + 1023) / 1024;

    cudaFuncSetAttribute(k_gemm_mma<8, 0>, cudaFuncAttributeMaxDynamicSharedMemorySize, SMEM_G);
    cudaFuncSetAttribute(k_gemm_mma<2, 1>, cudaFuncAttributeMaxDynamicSharedMemorySize, SMEM_G);

    // 0-2: splits + zero (proj path inputs), placed so launch #3 is the GEMM (ncu -s lands there)
    k_zero_cnt <<<(Nn + 255) / 256, 256>>>();
    k_split_x  <<<(Nn * FIN / 4 + 255) / 256, 256>>>(x);
    k_wsplit   <<<(Ll * Hh * Hh + FIN * Hh + 255) / 256, 256>>>(convW, projW);

    // 3: projection via mma path (bias+relu+split epilogue)
    k_gemm_mma<2, 1><<<dim3(MTILES, 2), 256, SMEM_G>>>(0, projb);

    // CSR build
    k_count_edges<<<(Ee + 255) / 256, 256>>>(ei);
    k_scan_block <<<SCAN_B, 1024>>>();
    k_scan_add   <<<SCAN_B, 1024>>>();
    k_csr_fill   <<<(Ee + 255) / 256, 256>>>(ei);

    // 4 GCN layers
    for (int l = 0; l < Ll; l++) {
        k_gemm_mma<8, 0><<<dim3(MTILES, 2), 256, SMEM_G>>>(l, nullptr);
        k_agg_fused<<<(Nn + 3) / 4, 256>>>(convb + l * Hh, gamma + l * Hh, beta + l * Hh,
                                           mean + l * Hh, var + l * Hh);
    }

    // pooling + head
    k_pool<<<Gg, 256>>>(batch);
    k_sgemm<<<dim3(Hh / 64, Gg / 64), 256>>>(W1, b1, Gg, Hh, 2 * Hh, 2);
    k_sgemm<<<dim3((Hh / 2) / 64, Gg / 64), 256>>>(W2, b2, Gg, Hh / 2, Hh, 3);
    k_head3<<<(Gg * Tt + 255) / 256, 256>>>(W3, b3, out);
}

// round 8
// speedup vs baseline: 2.2892x; 1.0564x over previous
#include <cuda_runtime.h>
#include <cuda_bf16.h>
#include <math.h>
#include <float.h>
#include <stdint.h>

#define Nn   50000
#define FIN  64
#define Hh   256
#define Ee   800000
#define Gg   2048
#define Ll   4
#define Tt   4
#define EPSc 1e-5f

#define MTILES ((Nn + 127) / 128)   // 391
#define Mpad   (MTILES * 128)       // 50048

// ---------------- scratch ----------------
__device__ __align__(16) float g_h [Nn * Hh];
__device__ __align__(16) float g_hW[(size_t)Mpad * Hh];
__device__ float g_isd[Nn];
__device__ int   g_cnt[Nn];
__device__ int   g_off[Nn + 1];
__device__ int   g_cur[Nn];
__device__ int   g_csr[Ee];
__device__ float g_wgt[Ee];
__device__ int   g_part[64];
__device__ __align__(16) float g_pool[Gg * 2 * Hh];
__device__ __align__(16) float g_f1[Gg * Hh];
__device__ __align__(16) float g_f2[Gg * (Hh / 2)];
__device__ __align__(16) __nv_bfloat16 g_Ahi[(size_t)Mpad * Hh];
__device__ __align__(16) __nv_bfloat16 g_Alo[(size_t)Mpad * Hh];
__device__ __align__(16) __nv_bfloat16 g_Bhi[Ll * Hh * Hh];
__device__ __align__(16) __nv_bfloat16 g_Blo[Ll * Hh * Hh];
__device__ __align__(16) __nv_bfloat16 g_Xhi[(size_t)Mpad * FIN];
__device__ __align__(16) __nv_bfloat16 g_Xlo[(size_t)Mpad * FIN];
__device__ __align__(16) __nv_bfloat16 g_PBhi[FIN * Hh];
__device__ __align__(16) __nv_bfloat16 g_PBlo[FIN * Hh];

// ---------------- asm helpers ----------------
__device__ __forceinline__ uint32_t smem_u32(const void* p) {
    uint32_t a;
    asm("{ .reg .u64 t; cvta.to.shared.u64 t, %1; cvt.u32.u64 %0, t; }" : "=r"(a) : "l"(p));
    return a;
}
#define CPA(dst, src) \
    asm volatile("cp.async.cg.shared.global [%0], [%1], 16;" :: "r"(dst), "l"(src) : "memory")
#define LDSM4(r, addr) \
    asm volatile("ldmatrix.sync.aligned.m8n8.x4.shared.b16 {%0,%1,%2,%3}, [%4];" \
        : "=r"((r)[0]), "=r"((r)[1]), "=r"((r)[2]), "=r"((r)[3]) : "r"(addr))
#define LDSM4T(r, addr) \
    asm volatile("ldmatrix.sync.aligned.m8n8.x4.trans.shared.b16 {%0,%1,%2,%3}, [%4];" \
        : "=r"((r)[0]), "=r"((r)[1]), "=r"((r)[2]), "=r"((r)[3]) : "r"(addr))
#define MMA16816(c, a, b) \
    asm volatile("mma.sync.aligned.m16n8k16.row.col.f32.bf16.bf16.f32 " \
        "{%0,%1,%2,%3}, {%4,%5,%6,%7}, {%8,%9}, {%0,%1,%2,%3};" \
        : "+f"((c)[0]), "+f"((c)[1]), "+f"((c)[2]), "+f"((c)[3]) \
        : "r"((a)[0]), "r"((a)[1]), "r"((a)[2]), "r"((a)[3]), "r"((b)[0]), "r"((b)[1]))

__device__ __forceinline__ uint32_t pack_hi2(float x, float y) {
    __nv_bfloat16 a = __float2bfloat16(x), b = __float2bfloat16(y);
    return ((uint32_t)*(uint16_t*)&b << 16) | *(uint16_t*)&a;
}
__device__ __forceinline__ uint32_t pack_lo2(float x, float y) {
    __nv_bfloat16 a = __float2bfloat16(x), b = __float2bfloat16(y);
    __nv_bfloat16 la = __float2bfloat16(x - __bfloat162float(a));
    __nv_bfloat16 lb = __float2bfloat16(y - __bfloat162float(b));
    return ((uint32_t)*(uint16_t*)&lb << 16) | *(uint16_t*)&la;
}

// ---------------- setup kernels ----------------
__global__ void k_zero_cnt() {
    int i = blockIdx.x * blockDim.x + threadIdx.x;
    if (i < Nn) g_cnt[i] = 0;
}
__global__ void k_split_x(const float* __restrict__ x) {
    int idx = blockIdx.x * blockDim.x + threadIdx.x;
    if (idx >= Nn * FIN / 4) return;
    float4 v = *(const float4*)&x[idx * 4];
    uint2 hv, lv;
    hv.x = pack_hi2(v.x, v.y); hv.y = pack_hi2(v.z, v.w);
    lv.x = pack_lo2(v.x, v.y); lv.y = pack_lo2(v.z, v.w);
    *(uint2*)&g_Xhi[idx * 4] = hv;
    *(uint2*)&g_Xlo[idx * 4] = lv;
}
__global__ void k_wsplit(const float* __restrict__ convW, const float* __restrict__ projW) {
    int idx = blockIdx.x * blockDim.x + threadIdx.x;
    if (idx < Ll * Hh * Hh) {
        float w = convW[idx];
        __nv_bfloat16 hi = __float2bfloat16(w);
        g_Bhi[idx] = hi;
        g_Blo[idx] = __float2bfloat16(w - __bfloat162float(hi));
    } else if (idx < Ll * Hh * Hh + FIN * Hh) {
        int j = idx - Ll * Hh * Hh;
        float w = projW[j];
        __nv_bfloat16 hi = __float2bfloat16(w);
        g_PBhi[j] = hi;
        g_PBlo[j] = __float2bfloat16(w - __bfloat162float(hi));
    }
}
__global__ void k_count_edges(const int* __restrict__ ei) {
    int e = blockIdx.x * blockDim.x + threadIdx.x;
    if (e < Ee) atomicAdd(&g_cnt[ei[Ee + e]], 1);
}
__global__ void k_scan_block() {
    __shared__ int s[1024];
    int gid = blockIdx.x * 1024 + threadIdx.x;
    int v = (gid < Nn) ? g_cnt[gid] : 0;
    s[threadIdx.x] = v;
    for (int d = 1; d < 1024; d <<= 1) {
        __syncthreads();
        int t = (threadIdx.x >= d) ? s[threadIdx.x - d] : 0;
        __syncthreads();
        s[threadIdx.x] += t;
    }
    __syncthreads();
    if (gid < Nn) g_off[gid] = s[threadIdx.x] - v;
    if (threadIdx.x == 1023) g_part[blockIdx.x] = s[1023];
}
__global__ void k_scan_add() {
    __shared__ int base;
    if (threadIdx.x == 0) {
        int acc = 0;
        for (int i = 0; i < blockIdx.x; i++) acc += g_part[i];
        base = acc;
    }
    __syncthreads();
    int gid = blockIdx.x * 1024 + threadIdx.x;
    if (gid < Nn) {
        int v = g_off[gid] + base;
        g_off[gid] = v;
        g_cur[gid] = v;
        g_isd[gid] = rsqrtf(1.0f + (float)g_cnt[gid]);
    }
    if (gid == 0) g_off[Nn] = Ee;
}
__global__ void k_csr_fill(const int* __restrict__ ei) {
    int e = blockIdx.x * blockDim.x + threadIdx.x;
    if (e < Ee) {
        int s = ei[e];
        int d = ei[Ee + e];
        int p = atomicAdd(&g_cur[d], 1);
        g_csr[p] = s;
        g_wgt[p] = g_isd[s] * g_isd[d];
    }
}

// ---------------- bf16x3 mma.sync GEMM, 4-slot K16 cp.async ring (2 CTAs/SM) ----------------
// MODE 0 (conv): A = g_Ahi/g_Alo [Mpad,256], B = g_Bhi/g_Blo + layer, C = g_hW
// MODE 1 (proj): A = g_Xhi/g_Xlo [Mpad,64],  B = g_PBhi/g_PBlo, C = relu(.+bias) -> g_h + split
// Slot (20992 B): A_hi[128x48B]=6144 | A_lo=6144 | B_hi[16x272B]=4352 | B_lo=4352
#define SLOT   20992
#define ALO_O  6144
#define BHI_O  12288
#define BLO_O  16640
#define SMEM_G (4 * SLOT)   // 83968

template<int KSTAGES, int MODE>
__global__ __launch_bounds__(256, 2) void k_gemm_mma(int layer, const float* __restrict__ bias) {
    extern __shared__ __align__(16) unsigned char smraw[];
    const int tid = threadIdx.x, lane = tid & 31, wid = tid >> 5;
    const int warp_m = wid & 3, warp_n = wid >> 2;
    const int m0 = blockIdx.x * 128, n0 = blockIdx.y * 128;
    const uint32_t sb = smem_u32(smraw);
    const int kdim = KSTAGES * 16;

    const __nv_bfloat16* Ah = (MODE == 0) ? g_Ahi : g_Xhi;
    const __nv_bfloat16* Al = (MODE == 0) ? g_Alo : g_Xlo;
    const __nv_bfloat16* Bh = (MODE == 0) ? g_Bhi + (size_t)layer * Hh * Hh : g_PBhi;
    const __nv_bfloat16* Bl = (MODE == 0) ? g_Blo + (size_t)layer * Hh * Hh : g_PBlo;

    // per-thread cp.async slots: A 128 rows x 2 chunks; B 16 rows x 16 chunks
    const int a_r = tid >> 1, a_c = tid & 1;
    const int b_r = tid >> 4, b_c = tid & 15;

#define LOAD_STAGE(slotbase, kt) do { \
        int k0 = (kt) * 16; \
        CPA((slotbase) + a_r * 48 + a_c * 16, \
            Ah + (size_t)(m0 + a_r) * kdim + k0 + a_c * 8); \
        CPA((slotbase) + ALO_O + a_r * 48 + a_c * 16, \
            Al + (size_t)(m0 + a_r) * kdim + k0 + a_c * 8); \
        CPA((slotbase) + BHI_O + b_r * 272 + b_c * 16, \
            Bh + (size_t)(k0 + b_r) * Hh + n0 + b_c * 8); \
        CPA((slotbase) + BLO_O + b_r * 272 + b_c * 16, \
            Bl + (size_t)(k0 + b_r) * Hh + n0 + b_c * 8); \
        asm volatile("cp.async.commit_group;" ::: "memory"); \
    } while (0)

    float acc[2][8][4];
    #pragma unroll
    for (int i = 0; i < 2; i++)
        #pragma unroll
        for (int j = 0; j < 8; j++)
            #pragma unroll
            for (int q = 0; q < 4; q++) acc[i][j][q] = 0.f;

    const uint32_t aoff = sb + (warp_m * 32 + (lane & 15)) * 48 + (lane >> 4) * 16;
    const uint32_t boff = sb + BHI_O + (lane & 15) * 272 + (warp_n * 8 + (lane >> 4)) * 16;

    LOAD_STAGE(sb, 0);
    LOAD_STAGE(sb + SLOT, 1);
    LOAD_STAGE(sb + 2 * SLOT, 2);

    #pragma unroll
    for (int kt = 0; kt < KSTAGES; kt++) {
        const uint32_t s = (kt & 3) * SLOT;
        asm volatile("cp.async.wait_group 2;" ::: "memory");
        __syncthreads();
        if (kt + 3 < KSTAGES) {
            LOAD_STAGE(sb + ((kt + 3) & 3) * SLOT, kt + 3);
        } else {
            asm volatile("cp.async.commit_group;" ::: "memory");
        }

        uint32_t ah[2][4], al[2][4], bh[4][4], bl[4][4];
        #pragma unroll
        for (int mt = 0; mt < 2; mt++) {
            LDSM4(ah[mt], aoff + s + mt * 768);
            LDSM4(al[mt], aoff + s + ALO_O + mt * 768);
        }
        #pragma unroll
        for (int nt = 0; nt < 4; nt++) {
            LDSM4T(bh[nt], boff + s + nt * 32);
            LDSM4T(bl[nt], boff + s + (BLO_O - BHI_O) + nt * 32);
        }
        #pragma unroll
        for (int mt = 0; mt < 2; mt++)
            #pragma unroll
            for (int nt = 0; nt < 4; nt++)
                #pragma unroll
                for (int nb = 0; nb < 2; nb++) {
                    float* c = acc[mt][nt * 2 + nb];
                    MMA16816(c, ah[mt], &bh[nt][nb * 2]);
                    MMA16816(c, ah[mt], &bl[nt][nb * 2]);
                    MMA16816(c, al[mt], &bh[nt][nb * 2]);
                }
    }
#undef LOAD_STAGE

    #pragma unroll
    for (int mt = 0; mt < 2; mt++) {
        int rbase = m0 + warp_m * 32 + mt * 16 + (lane >> 2);
        #pragma unroll
        for (int half = 0; half < 2; half++) {
            int r = rbase + half * 8;
            #pragma unroll
            for (int j = 0; j < 8; j++) {
                int n = n0 + warp_n * 64 + j * 8 + (lane & 3) * 2;
                float vx = acc[mt][j][half * 2 + 0];
                float vy = acc[mt][j][half * 2 + 1];
                if (MODE == 0) {
                    float2 v = {vx, vy};
                    *(float2*)&g_hW[(size_t)r * Hh + n] = v;
                } else if (r < Nn) {
                    float2 bi = *(const float2*)&bias[n];
                    vx = fmaxf(vx + bi.x, 0.f);
                    vy = fmaxf(vy + bi.y, 0.f);
                    float2 v = {vx, vy};
                    *(float2*)&g_h[(size_t)r * Hh + n] = v;
                    *(uint32_t*)&g_Ahi[(size_t)r * Hh + n] = pack_hi2(vx, vy);
                    *(uint32_t*)&g_Alo[(size_t)r * Hh + n] = pack_lo2(vx, vy);
                }
            }
        }
    }
}

// ---------------- SIMT SGEMM (head only) ----------------
__global__ void k_sgemm(const float* __restrict__ B, const float* __restrict__ bias,
                        int M, int N, int K, int sel) {
    const float* A = (sel == 2) ? g_pool : g_f1;
    float*       C = (sel == 2) ? g_f1  : g_f2;

    __shared__ float As[16][64];
    __shared__ float Bs[16][68];

    int tid = threadIdx.x;
    int m0 = blockIdx.y * 64, n0 = blockIdx.x * 64;
    int tr = tid >> 4, tc = tid & 15;
    int arow = tid >> 2, aq = (tid & 3) * 4;
    int brow = tid >> 4, bq = (tid & 15) * 4;

    float acc[4][4];
    #pragma unroll
    for (int i = 0; i < 4; i++)
        #pragma unroll
        for (int j = 0; j < 4; j++) acc[i][j] = 0.f;

    for (int k0 = 0; k0 < K; k0 += 16) {
        float4 av;
        if (m0 + arow < M)
            av = *reinterpret_cast<const float4*>(&A[(size_t)(m0 + arow) * K + k0 + aq]);
        else
            av = make_float4(0.f, 0.f, 0.f, 0.f);
        As[aq + 0][arow] = av.x;
        As[aq + 1][arow] = av.y;
        As[aq + 2][arow] = av.z;
        As[aq + 3][arow] = av.w;

        float4 bv = *reinterpret_cast<const float4*>(&B[(size_t)(k0 + brow) * N + n0 + bq]);
        Bs[brow][bq + 0] = bv.x;
        Bs[brow][bq + 1] = bv.y;
        Bs[brow][bq + 2] = bv.z;
        Bs[brow][bq + 3] = bv.w;
        __syncthreads();

        #pragma unroll
        for (int k = 0; k < 16; k++) {
            float arr[4], br[4];
            #pragma unroll
            for (int i = 0; i < 4; i++) arr[i] = As[k][tr * 4 + i];
            #pragma unroll
            for (int j = 0; j < 4; j++) br[j] = Bs[k][tc * 4 + j];
            #pragma unroll
            for (int i = 0; i < 4; i++)
                #pragma unroll
                for (int j = 0; j < 4; j++) acc[i][j] = fmaf(arr[i], br[j], acc[i][j]);
        }
        __syncthreads();
    }

    #pragma unroll
    for (int i = 0; i < 4; i++) {
        int m = m0 + tr * 4 + i;
        if (m >= M) continue;
        #pragma unroll
        for (int j = 0; j < 4; j++) {
            int n = n0 + tc * 4 + j;
            float v = fmaxf(acc[i][j] + bias[n], 0.f);
            C[(size_t)m * N + n] = v;
        }
    }
}

// ---------------- fused aggregation + bias + BN + ReLU + residual + bf16 split ----------------
__global__ __launch_bounds__(256) void k_agg_fused(
        const float* __restrict__ bias, const float* __restrict__ gamma,
        const float* __restrict__ beta, const float* __restrict__ mean,
        const float* __restrict__ var) {
    int v = blockIdx.x * 4 + (threadIdx.x >> 6);
    if (v >= Nn) return;
    int c = (threadIdx.x & 63) * 4;

    float idv = g_isd[v];
    float ws = idv * idv;
    float4 acc = *(const float4*)&g_hW[(size_t)v * Hh + c];
    acc.x *= ws; acc.y *= ws; acc.z *= ws; acc.w *= ws;

    int j = g_off[v], e = g_off[v + 1];
    for (; j + 4 <= e; j += 4) {
        int u0 = g_csr[j], u1 = g_csr[j + 1], u2 = g_csr[j + 2], u3 = g_csr[j + 3];
        float w0 = g_wgt[j], w1 = g_wgt[j + 1], w2 = g_wgt[j + 2], w3 = g_wgt[j + 3];
        float4 r0 = *(const float4*)&g_hW[(size_t)u0 * Hh + c];
        float4 r1 = *(const float4*)&g_hW[(size_t)u1 * Hh + c];
        float4 r2 = *(const float4*)&g_hW[(size_t)u2 * Hh + c];
        float4 r3 = *(const float4*)&g_hW[(size_t)u3 * Hh + c];
        acc.x = fmaf(r0.x, w0, fmaf(r1.x, w1, fmaf(r2.x, w2, fmaf(r3.x, w3, acc.x))));
        acc.y = fmaf(r0.y, w0, fmaf(r1.y, w1, fmaf(r2.y, w2, fmaf(r3.y, w3, acc.y))));
        acc.z = fmaf(r0.z, w0, fmaf(r1.z, w1, fmaf(r2.z, w2, fmaf(r3.z, w3, acc.z))));
        acc.w = fmaf(r0.w, w0, fmaf(r1.w, w1, fmaf(r2.w, w2, fmaf(r3.w, w3, acc.w))));
    }
    for (; j < e; j++) {
        int u = g_csr[j];
        float w = g_wgt[j];
        float4 r = *(const float4*)&g_hW[(size_t)u * Hh + c];
        acc.x = fmaf(r.x, w, acc.x);
        acc.y = fmaf(r.y, w, acc.y);
        acc.z = fmaf(r.z, w, acc.z);
        acc.w = fmaf(r.w, w, acc.w);
    }

    float4 bi = *(const float4*)&bias[c];
    float4 ga = *(const float4*)&gamma[c];
    float4 be = *(const float4*)&beta[c];
    float4 me = *(const float4*)&mean[c];
    float4 va = *(const float4*)&var[c];
    float4 res = *(const float4*)&g_h[(size_t)v * Hh + c];

    float4 o;
    o.x = fmaxf((acc.x + bi.x - me.x) * (ga.x * rsqrtf(va.x + EPSc)) + be.x, 0.f) + res.x;
    o.y = fmaxf((acc.y + bi.y - me.y) * (ga.y * rsqrtf(va.y + EPSc)) + be.y, 0.f) + res.y;
    o.z = fmaxf((acc.z + bi.z - me.z) * (ga.z * rsqrtf(va.z + EPSc)) + be.z, 0.f) + res.z;
    o.w = fmaxf((acc.w + bi.w - me.w) * (ga.w * rsqrtf(va.w + EPSc)) + be.w, 0.f) + res.w;
    *(float4*)&g_h[(size_t)v * Hh + c] = o;

    uint2 hv, lv;
    hv.x = pack_hi2(o.x, o.y); hv.y = pack_hi2(o.z, o.w);
    lv.x = pack_lo2(o.x, o.y); lv.y = pack_lo2(o.z, o.w);
    *(uint2*)&g_Ahi[(size_t)v * Hh + c] = hv;
    *(uint2*)&g_Alo[(size_t)v * Hh + c] = lv;
}

// ---------------- pooling ----------------
__global__ void k_pool(const int* __restrict__ batch) {
    __shared__ int sbb[2];
    int grp = blockIdx.x, t = threadIdx.x;
    if (t < 2) {
        int key = grp + t;
        int lo = 0, hi = Nn;
        while (lo < hi) {
            int mid = (lo + hi) >> 1;
            if (batch[mid] < key) lo = mid + 1; else hi = mid;
        }
        sbb[t] = lo;
    }
    __syncthreads();
    int s = sbb[0], e = sbb[1];
    float sum = 0.f, mx = -FLT_MAX;
    for (int i = s; i < e; i++) {
        float v = g_h[(size_t)i * Hh + t];
        sum += v;
        mx = fmaxf(mx, v);
    }
    float c = (float)(e - s);
    g_pool[(size_t)grp * (2 * Hh) + t]      = sum / fmaxf(c, 1.f);
    g_pool[(size_t)grp * (2 * Hh) + Hh + t] = mx;
}

// ---------------- final tiny GEMM ----------------
__global__ void k_head3(const float* __restrict__ W, const float* __restrict__ b,
                        float* __restrict__ out) {
    int idx = blockIdx.x * blockDim.x + threadIdx.x;
    if (idx >= Gg * Tt) return;
    int r = idx >> 2, c = idx & 3;
    float acc = b[c];
    const float* row = &g_f2[(size_t)r * 128];
    #pragma unroll 8
    for (int k = 0; k < 128; k++) acc = fmaf(row[k], W[k * 4 + c], acc);
    out[idx] = acc;
}

// ---------------- launch ----------------
extern "C" void kernel_launch(void* const* d_in, const int* in_sizes, int n_in,
                              void* d_out, int out_size) {
    const float* x     = (const float*)d_in[0];
    const int*   ei    = (const int*)d_in[1];
    const int*   batch = (const int*)d_in[2];
    const float* projW = (const float*)d_in[3];
    const float* projb = (const float*)d_in[4];
    const float* convW = (const float*)d_in[5];
    const float* convb = (const float*)d_in[6];
    const float* gamma = (const float*)d_in[7];
    const float* beta  = (const float*)d_in[8];
    const float* mean  = (const float*)d_in[9];
    const float* var   = (const float*)d_in[10];
    const float* W1 = (const float*)d_in[11];
    const float* b1 = (const float*)d_in[12];
    const float* W2 = (const float*)d_in[13];
    const float* b2 = (const float*)d_in[14];
    const float* W3 = (const float*)d_in[15];
    const float* b3 = (const float*)d_in[16];
    float* out = (float*)d_out;

    const int SCAN_B = (Nn + 1023) / 1024;

    cudaFuncSetAttribute(k_gemm_mma<16, 0>, cudaFuncAttributeMaxDynamicSharedMemorySize, SMEM_G);
    cudaFuncSetAttribute(k_gemm_mma<4, 1>, cudaFuncAttributeMaxDynamicSharedMemorySize, SMEM_G);

    // 0-2: splits + zero; launch #3 is the conv-shaped GEMM (ncu -s 5 -c 1 lands nearby)
    k_zero_cnt <<<(Nn + 255) / 256, 256>>>();
    k_split_x  <<<(Nn * FIN / 4 + 255) / 256, 256>>>(x);
    k_wsplit   <<<(Ll * Hh * Hh + FIN * Hh + 255) / 256, 256>>>(convW, projW);

    // 3: projection via mma path
    k_gemm_mma<4, 1><<<dim3(MTILES, 2), 256, SMEM_G>>>(0, projb);

    // CSR build
    k_count_edges<<<(Ee + 255) / 256, 256>>>(ei);
    k_scan_block <<<SCAN_B, 1024>>>();
    k_scan_add   <<<SCAN_B, 1024>>>();
    k_csr_fill   <<<(Ee + 255) / 256, 256>>>(ei);

    // 4 GCN layers
    for (int l = 0; l < Ll; l++) {
        k_gemm_mma<16, 0><<<dim3(MTILES, 2), 256, SMEM_G>>>(l, nullptr);
        k_agg_fused<<<(Nn + 3) / 4, 256>>>(convb + l * Hh, gamma + l * Hh, beta + l * Hh,
                                           mean + l * Hh, var + l * Hh);
    }

    // pooling + head
    k_pool<<<Gg, 256>>>(batch);
    k_sgemm<<<dim3(Hh / 64, Gg / 64), 256>>>(W1, b1, Gg, Hh, 2 * Hh, 2);
    k_sgemm<<<dim3((Hh / 2) / 64, Gg / 64), 256>>>(W2, b2, Gg, Hh / 2, Hh, 3);
    k_head3<<<(Gg * Tt + 255) / 256, 256>>>(W3, b3, out);
}

// round 9
// speedup vs baseline: 2.4293x; 1.0612x over previous
#include <cuda_runtime.h>
#include <cuda_bf16.h>
#include <cuda_fp16.h>
#include <math.h>
#include <float.h>
#include <stdint.h>

#define Nn   50000
#define FIN  64
#define Hh   256
#define Ee   800000
#define Gg   2048
#define Ll   4
#define Tt   4
#define EPSc 1e-5f

#define MTILES ((Nn + 127) / 128)   // 391
#define Mpad   (MTILES * 128)       // 50048

// ---------------- scratch ----------------
__device__ __align__(16) float  g_h  [Nn * Hh];
__device__ __align__(16) __half g_hWh[(size_t)Mpad * Hh];   // fp16 message rows
__device__ float g_isd[Nn];
__device__ int   g_cnt[Nn];
__device__ int   g_off[Nn + 1];
__device__ int   g_cur[Nn];
__device__ int   g_csr[Ee];
__device__ float g_wgt[Ee];
__device__ int   g_part[64];
__device__ __align__(16) float g_pool[Gg * 2 * Hh];
__device__ __align__(16) float g_f1[Gg * Hh];
__device__ __align__(16) float g_f2[Gg * (Hh / 2)];
__device__ __align__(16) __nv_bfloat16 g_Ahi[(size_t)Mpad * Hh];
__device__ __align__(16) __nv_bfloat16 g_Alo[(size_t)Mpad * Hh];
__device__ __align__(16) __nv_bfloat16 g_Bhi[Ll * Hh * Hh];
__device__ __align__(16) __nv_bfloat16 g_Blo[Ll * Hh * Hh];
__device__ __align__(16) __nv_bfloat16 g_Xhi[(size_t)Mpad * FIN];
__device__ __align__(16) __nv_bfloat16 g_Xlo[(size_t)Mpad * FIN];
__device__ __align__(16) __nv_bfloat16 g_PBhi[FIN * Hh];
__device__ __align__(16) __nv_bfloat16 g_PBlo[FIN * Hh];

// ---------------- asm helpers ----------------
__device__ __forceinline__ uint32_t smem_u32(const void* p) {
    uint32_t a;
    asm("{ .reg .u64 t; cvta.to.shared.u64 t, %1; cvt.u32.u64 %0, t; }" : "=r"(a) : "l"(p));
    return a;
}
#define CPA(dst, src) \
    asm volatile("cp.async.cg.shared.global [%0], [%1], 16;" :: "r"(dst), "l"(src) : "memory")
#define LDSM4(r, addr) \
    asm volatile("ldmatrix.sync.aligned.m8n8.x4.shared.b16 {%0,%1,%2,%3}, [%4];" \
        : "=r"((r)[0]), "=r"((r)[1]), "=r"((r)[2]), "=r"((r)[3]) : "r"(addr))
#define LDSM4T(r, addr) \
    asm volatile("ldmatrix.sync.aligned.m8n8.x4.trans.shared.b16 {%0,%1,%2,%3}, [%4];" \
        : "=r"((r)[0]), "=r"((r)[1]), "=r"((r)[2]), "=r"((r)[3]) : "r"(addr))
#define MMA16816(c, a, b) \
    asm volatile("mma.sync.aligned.m16n8k16.row.col.f32.bf16.bf16.f32 " \
        "{%0,%1,%2,%3}, {%4,%5,%6,%7}, {%8,%9}, {%0,%1,%2,%3};" \
        : "+f"((c)[0]), "+f"((c)[1]), "+f"((c)[2]), "+f"((c)[3]) \
        : "r"((a)[0]), "r"((a)[1]), "r"((a)[2]), "r"((a)[3]), "r"((b)[0]), "r"((b)[1]))

__device__ __forceinline__ uint32_t pack_hi2(float x, float y) {
    __nv_bfloat16 a = __float2bfloat16(x), b = __float2bfloat16(y);
    return ((uint32_t)*(uint16_t*)&b << 16) | *(uint16_t*)&a;
}
__device__ __forceinline__ uint32_t pack_lo2(float x, float y) {
    __nv_bfloat16 a = __float2bfloat16(x), b = __float2bfloat16(y);
    __nv_bfloat16 la = __float2bfloat16(x - __bfloat162float(a));
    __nv_bfloat16 lb = __float2bfloat16(y - __bfloat162float(b));
    return ((uint32_t)*(uint16_t*)&lb << 16) | *(uint16_t*)&la;
}

// ---------------- setup kernels ----------------
__global__ void k_zero_cnt() {
    int i = blockIdx.x * blockDim.x + threadIdx.x;
    if (i < Nn) g_cnt[i] = 0;
}
__global__ void k_split_x(const float* __restrict__ x) {
    int idx = blockIdx.x * blockDim.x + threadIdx.x;
    if (idx >= Nn * FIN / 4) return;
    float4 v = *(const float4*)&x[idx * 4];
    uint2 hv, lv;
    hv.x = pack_hi2(v.x, v.y); hv.y = pack_hi2(v.z, v.w);
    lv.x = pack_lo2(v.x, v.y); lv.y = pack_lo2(v.z, v.w);
    *(uint2*)&g_Xhi[idx * 4] = hv;
    *(uint2*)&g_Xlo[idx * 4] = lv;
}
__global__ void k_wsplit(const float* __restrict__ convW, const float* __restrict__ projW) {
    int idx = blockIdx.x * blockDim.x + threadIdx.x;
    if (idx < Ll * Hh * Hh) {
        float w = convW[idx];
        __nv_bfloat16 hi = __float2bfloat16(w);
        g_Bhi[idx] = hi;
        g_Blo[idx] = __float2bfloat16(w - __bfloat162float(hi));
    } else if (idx < Ll * Hh * Hh + FIN * Hh) {
        int j = idx - Ll * Hh * Hh;
        float w = projW[j];
        __nv_bfloat16 hi = __float2bfloat16(w);
        g_PBhi[j] = hi;
        g_PBlo[j] = __float2bfloat16(w - __bfloat162float(hi));
    }
}
__global__ void k_count_edges(const int* __restrict__ ei) {
    int e = blockIdx.x * blockDim.x + threadIdx.x;
    if (e < Ee) atomicAdd(&g_cnt[ei[Ee + e]], 1);
}
__global__ void k_scan_block() {
    __shared__ int s[1024];
    int gid = blockIdx.x * 1024 + threadIdx.x;
    int v = (gid < Nn) ? g_cnt[gid] : 0;
    s[threadIdx.x] = v;
    for (int d = 1; d < 1024; d <<= 1) {
        __syncthreads();
        int t = (threadIdx.x >= d) ? s[threadIdx.x - d] : 0;
        __syncthreads();
        s[threadIdx.x] += t;
    }
    __syncthreads();
    if (gid < Nn) g_off[gid] = s[threadIdx.x] - v;
    if (threadIdx.x == 1023) g_part[blockIdx.x] = s[1023];
}
__global__ void k_scan_add() {
    __shared__ int base;
    if (threadIdx.x == 0) {
        int acc = 0;
        for (int i = 0; i < blockIdx.x; i++) acc += g_part[i];
        base = acc;
    }
    __syncthreads();
    int gid = blockIdx.x * 1024 + threadIdx.x;
    if (gid < Nn) {
        int v = g_off[gid] + base;
        g_off[gid] = v;
        g_cur[gid] = v;
        g_isd[gid] = rsqrtf(1.0f + (float)g_cnt[gid]);
    }
    if (gid == 0) g_off[Nn] = Ee;
}
__global__ void k_csr_fill(const int* __restrict__ ei) {
    int e = blockIdx.x * blockDim.x + threadIdx.x;
    if (e < Ee) {
        int s = ei[e];
        int d = ei[Ee + e];
        int p = atomicAdd(&g_cur[d], 1);
        g_csr[p] = s;
        g_wgt[p] = g_isd[s] * g_isd[d];
    }
}

// ---------------- bf16x3 mma.sync GEMM, 4-slot K16 cp.async ring ----------------
// MODE 0 (conv): A = g_Ahi/g_Alo [Mpad,256], B = g_Bhi/g_Blo + layer, C = g_hWh (fp16)
// MODE 1 (proj): A = g_Xhi/g_Xlo [Mpad,64],  B = g_PBhi/g_PBlo, C = relu(.+bias) -> g_h + split
#define SLOT   20992
#define ALO_O  6144
#define BHI_O  12288
#define BLO_O  16640
#define SMEM_G (4 * SLOT)   // 83968

template<int KSTAGES, int MODE>
__global__ __launch_bounds__(256, 2) void k_gemm_mma(int layer, const float* __restrict__ bias) {
    extern __shared__ __align__(16) unsigned char smraw[];
    const int tid = threadIdx.x, lane = tid & 31, wid = tid >> 5;
    const int warp_m = wid & 3, warp_n = wid >> 2;
    const int m0 = blockIdx.x * 128, n0 = blockIdx.y * 128;
    const uint32_t sb = smem_u32(smraw);
    const int kdim = KSTAGES * 16;

    const __nv_bfloat16* Ah = (MODE == 0) ? g_Ahi : g_Xhi;
    const __nv_bfloat16* Al = (MODE == 0) ? g_Alo : g_Xlo;
    const __nv_bfloat16* Bh = (MODE == 0) ? g_Bhi + (size_t)layer * Hh * Hh : g_PBhi;
    const __nv_bfloat16* Bl = (MODE == 0) ? g_Blo + (size_t)layer * Hh * Hh : g_PBlo;

    const int a_r = tid >> 1, a_c = tid & 1;
    const int b_r = tid >> 4, b_c = tid & 15;

#define LOAD_STAGE(slotbase, kt) do { \
        int k0 = (kt) * 16; \
        CPA((slotbase) + a_r * 48 + a_c * 16, \
            Ah + (size_t)(m0 + a_r) * kdim + k0 + a_c * 8); \
        CPA((slotbase) + ALO_O + a_r * 48 + a_c * 16, \
            Al + (size_t)(m0 + a_r) * kdim + k0 + a_c * 8); \
        CPA((slotbase) + BHI_O + b_r * 272 + b_c * 16, \
            Bh + (size_t)(k0 + b_r) * Hh + n0 + b_c * 8); \
        CPA((slotbase) + BLO_O + b_r * 272 + b_c * 16, \
            Bl + (size_t)(k0 + b_r) * Hh + n0 + b_c * 8); \
        asm volatile("cp.async.commit_group;" ::: "memory"); \
    } while (0)

    float acc[2][8][4];
    #pragma unroll
    for (int i = 0; i < 2; i++)
        #pragma unroll
        for (int j = 0; j < 8; j++)
            #pragma unroll
            for (int q = 0; q < 4; q++) acc[i][j][q] = 0.f;

    const uint32_t aoff = sb + (warp_m * 32 + (lane & 15)) * 48 + (lane >> 4) * 16;
    const uint32_t boff = sb + BHI_O + (lane & 15) * 272 + (warp_n * 8 + (lane >> 4)) * 16;

    LOAD_STAGE(sb, 0);
    LOAD_STAGE(sb + SLOT, 1);
    LOAD_STAGE(sb + 2 * SLOT, 2);

    #pragma unroll
    for (int kt = 0; kt < KSTAGES; kt++) {
        const uint32_t s = (kt & 3) * SLOT;
        asm volatile("cp.async.wait_group 2;" ::: "memory");
        __syncthreads();
        if (kt + 3 < KSTAGES) {
            LOAD_STAGE(sb + ((kt + 3) & 3) * SLOT, kt + 3);
        } else {
            asm volatile("cp.async.commit_group;" ::: "memory");
        }

        uint32_t ah[2][4], al[2][4], bh[4][4], bl[4][4];
        #pragma unroll
        for (int mt = 0; mt < 2; mt++) {
            LDSM4(ah[mt], aoff + s + mt * 768);
            LDSM4(al[mt], aoff + s + ALO_O + mt * 768);
        }
        #pragma unroll
        for (int nt = 0; nt < 4; nt++) {
            LDSM4T(bh[nt], boff + s + nt * 32);
            LDSM4T(bl[nt], boff + s + (BLO_O - BHI_O) + nt * 32);
        }
        #pragma unroll
        for (int mt = 0; mt < 2; mt++)
            #pragma unroll
            for (int nt = 0; nt < 4; nt++)
                #pragma unroll
                for (int nb = 0; nb < 2; nb++) {
                    float* c = acc[mt][nt * 2 + nb];
                    MMA16816(c, ah[mt], &bh[nt][nb * 2]);
                    MMA16816(c, ah[mt], &bl[nt][nb * 2]);
                    MMA16816(c, al[mt], &bh[nt][nb * 2]);
                }
    }
#undef LOAD_STAGE

    #pragma unroll
    for (int mt = 0; mt < 2; mt++) {
        int rbase = m0 + warp_m * 32 + mt * 16 + (lane >> 2);
        #pragma unroll
        for (int half = 0; half < 2; half++) {
            int r = rbase + half * 8;
            #pragma unroll
            for (int j = 0; j < 8; j++) {
                int n = n0 + warp_n * 64 + j * 8 + (lane & 3) * 2;
                float vx = acc[mt][j][half * 2 + 0];
                float vy = acc[mt][j][half * 2 + 1];
                if (MODE == 0) {
                    __half2 hv = __floats2half2_rn(vx, vy);
                    *(__half2*)&g_hWh[(size_t)r * Hh + n] = hv;
                } else if (r < Nn) {
                    float2 bi = *(const float2*)&bias[n];
                    vx = fmaxf(vx + bi.x, 0.f);
                    vy = fmaxf(vy + bi.y, 0.f);
                    float2 v = {vx, vy};
                    *(float2*)&g_h[(size_t)r * Hh + n] = v;
                    *(uint32_t*)&g_Ahi[(size_t)r * Hh + n] = pack_hi2(vx, vy);
                    *(uint32_t*)&g_Alo[(size_t)r * Hh + n] = pack_lo2(vx, vy);
                }
            }
        }
    }
}

// ---------------- SIMT SGEMM (head only) ----------------
__global__ void k_sgemm(const float* __restrict__ B, const float* __restrict__ bias,
                        int M, int N, int K, int sel) {
    const float* A = (sel == 2) ? g_pool : g_f1;
    float*       C = (sel == 2) ? g_f1  : g_f2;

    __shared__ float As[16][64];
    __shared__ float Bs[16][68];

    int tid = threadIdx.x;
    int m0 = blockIdx.y * 64, n0 = blockIdx.x * 64;
    int tr = tid >> 4, tc = tid & 15;
    int arow = tid >> 2, aq = (tid & 3) * 4;
    int brow = tid >> 4, bq = (tid & 15) * 4;

    float acc[4][4];
    #pragma unroll
    for (int i = 0; i < 4; i++)
        #pragma unroll
        for (int j = 0; j < 4; j++) acc[i][j] = 0.f;

    for (int k0 = 0; k0 < K; k0 += 16) {
        float4 av;
        if (m0 + arow < M)
            av = *reinterpret_cast<const float4*>(&A[(size_t)(m0 + arow) * K + k0 + aq]);
        else
            av = make_float4(0.f, 0.f, 0.f, 0.f);
        As[aq + 0][arow] = av.x;
        As[aq + 1][arow] = av.y;
        As[aq + 2][arow] = av.z;
        As[aq + 3][arow] = av.w;

        float4 bv = *reinterpret_cast<const float4*>(&B[(size_t)(k0 + brow) * N + n0 + bq]);
        Bs[brow][bq + 0] = bv.x;
        Bs[brow][bq + 1] = bv.y;
        Bs[brow][bq + 2] = bv.z;
        Bs[brow][bq + 3] = bv.w;
        __syncthreads();

        #pragma unroll
        for (int k = 0; k < 16; k++) {
            float arr[4], br[4];
            #pragma unroll
            for (int i = 0; i < 4; i++) arr[i] = As[k][tr * 4 + i];
            #pragma unroll
            for (int j = 0; j < 4; j++) br[j] = Bs[k][tc * 4 + j];
            #pragma unroll
            for (int i = 0; i < 4; i++)
                #pragma unroll
                for (int j = 0; j < 4; j++) acc[i][j] = fmaf(arr[i], br[j], acc[i][j]);
        }
        __syncthreads();
    }

    #pragma unroll
    for (int i = 0; i < 4; i++) {
        int m = m0 + tr * 4 + i;
        if (m >= M) continue;
        #pragma unroll
        for (int j = 0; j < 4; j++) {
            int n = n0 + tc * 4 + j;
            float v = fmaxf(acc[i][j] + bias[n], 0.f);
            C[(size_t)m * N + n] = v;
        }
    }
}

// ---------------- fused aggregation (fp16 messages) + BN + ReLU + residual + split ----------------
__global__ __launch_bounds__(256) void k_agg_fused(
        const float* __restrict__ bias, const float* __restrict__ gamma,
        const float* __restrict__ beta, const float* __restrict__ mean,
        const float* __restrict__ var) {
    int v = blockIdx.x * 4 + (threadIdx.x >> 6);
    if (v >= Nn) return;
    int c = (threadIdx.x & 63) * 4;

    float idv = g_isd[v];
    float ws = idv * idv;

    uint2 sr = *(const uint2*)&g_hWh[(size_t)v * Hh + c];
    float2 s0 = __half22float2(*(__half2*)&sr.x);
    float2 s1 = __half22float2(*(__half2*)&sr.y);
    float4 acc = {s0.x * ws, s0.y * ws, s1.x * ws, s1.y * ws};

    int j = g_off[v], e = g_off[v + 1];
    for (; j + 4 <= e; j += 4) {
        int u0 = g_csr[j], u1 = g_csr[j + 1], u2 = g_csr[j + 2], u3 = g_csr[j + 3];
        float w0 = g_wgt[j], w1 = g_wgt[j + 1], w2 = g_wgt[j + 2], w3 = g_wgt[j + 3];
        uint2 q0 = *(const uint2*)&g_hWh[(size_t)u0 * Hh + c];
        uint2 q1 = *(const uint2*)&g_hWh[(size_t)u1 * Hh + c];
        uint2 q2 = *(const uint2*)&g_hWh[(size_t)u2 * Hh + c];
        uint2 q3 = *(const uint2*)&g_hWh[(size_t)u3 * Hh + c];
        float2 a0 = __half22float2(*(__half2*)&q0.x), b0 = __half22float2(*(__half2*)&q0.y);
        float2 a1 = __half22float2(*(__half2*)&q1.x), b1 = __half22float2(*(__half2*)&q1.y);
        float2 a2 = __half22float2(*(__half2*)&q2.x), b2 = __half22float2(*(__half2*)&q2.y);
        float2 a3 = __half22float2(*(__half2*)&q3.x), b3 = __half22float2(*(__half2*)&q3.y);
        acc.x = fmaf(a0.x, w0, fmaf(a1.x, w1, fmaf(a2.x, w2, fmaf(a3.x, w3, acc.x))));
        acc.y = fmaf(a0.y, w0, fmaf(a1.y, w1, fmaf(a2.y, w2, fmaf(a3.y, w3, acc.y))));
        acc.z = fmaf(b0.x, w0, fmaf(b1.x, w1, fmaf(b2.x, w2, fmaf(b3.x, w3, acc.z))));
        acc.w = fmaf(b0.y, w0, fmaf(b1.y, w1, fmaf(b2.y, w2, fmaf(b3.y, w3, acc.w))));
    }
    for (; j < e; j++) {
        int u = g_csr[j];
        float w = g_wgt[j];
        uint2 q = *(const uint2*)&g_hWh[(size_t)u * Hh + c];
        float2 a = __half22float2(*(__half2*)&q.x), b = __half22float2(*(__half2*)&q.y);
        acc.x = fmaf(a.x, w, acc.x);
        acc.y = fmaf(a.y, w, acc.y);
        acc.z = fmaf(b.x, w, acc.z);
        acc.w = fmaf(b.y, w, acc.w);
    }

    float4 bi = *(const float4*)&bias[c];
    float4 ga = *(const float4*)&gamma[c];
    float4 be = *(const float4*)&beta[c];
    float4 me = *(const float4*)&mean[c];
    float4 va = *(const float4*)&var[c];
    float4 res = *(const float4*)&g_h[(size_t)v * Hh + c];

    float4 o;
    o.x = fmaxf((acc.x + bi.x - me.x) * (ga.x * rsqrtf(va.x + EPSc)) + be.x, 0.f) + res.x;
    o.y = fmaxf((acc.y + bi.y - me.y) * (ga.y * rsqrtf(va.y + EPSc)) + be.y, 0.f) + res.y;
    o.z = fmaxf((acc.z + bi.z - me.z) * (ga.z * rsqrtf(va.z + EPSc)) + be.z, 0.f) + res.z;
    o.w = fmaxf((acc.w + bi.w - me.w) * (ga.w * rsqrtf(va.w + EPSc)) + be.w, 0.f) + res.w;
    *(float4*)&g_h[(size_t)v * Hh + c] = o;

    uint2 hv, lv;
    hv.x = pack_hi2(o.x, o.y); hv.y = pack_hi2(o.z, o.w);
    lv.x = pack_lo2(o.x, o.y); lv.y = pack_lo2(o.z, o.w);
    *(uint2*)&g_Ahi[(size_t)v * Hh + c] = hv;
    *(uint2*)&g_Alo[(size_t)v * Hh + c] = lv;
}

// ---------------- pooling ----------------
__global__ void k_pool(const int* __restrict__ batch) {
    __shared__ int sbb[2];
    int grp = blockIdx.x, t = threadIdx.x;
    if (t < 2) {
        int key = grp + t;
        int lo = 0, hi = Nn;
        while (lo < hi) {
            int mid = (lo + hi) >> 1;
            if (batch[mid] < key) lo = mid + 1; else hi = mid;
        }
        sbb[t] = lo;
    }
    __syncthreads();
    int s = sbb[0], e = sbb[1];
    float sum = 0.f, mx = -FLT_MAX;
    for (int i = s; i < e; i++) {
        float v = g_h[(size_t)i * Hh + t];
        sum += v;
        mx = fmaxf(mx, v);
    }
    float c = (float)(e - s);
    g_pool[(size_t)grp * (2 * Hh) + t]      = sum / fmaxf(c, 1.f);
    g_pool[(size_t)grp * (2 * Hh) + Hh + t] = mx;
}

// ---------------- final tiny GEMM ----------------
__global__ void k_head3(const float* __restrict__ W, const float* __restrict__ b,
                        float* __restrict__ out) {
    int idx = blockIdx.x * blockDim.x + threadIdx.x;
    if (idx >= Gg * Tt) return;
    int r = idx >> 2, c = idx & 3;
    float acc = b[c];
    const float* row = &g_f2[(size_t)r * 128];
    #pragma unroll 8
    for (int k = 0; k < 128; k++) acc = fmaf(row[k], W[k * 4 + c], acc);
    out[idx] = acc;
}

// ---------------- launch ----------------
extern "C" void kernel_launch(void* const* d_in, const int* in_sizes, int n_in,
                              void* d_out, int out_size) {
    const float* x     = (const float*)d_in[0];
    const int*   ei    = (const int*)d_in[1];
    const int*   batch = (const int*)d_in[2];
    const float* projW = (const float*)d_in[3];
    const float* projb = (const float*)d_in[4];
    const float* convW = (const float*)d_in[5];
    const float* convb = (const float*)d_in[6];
    const float* gamma = (const float*)d_in[7];
    const float* beta  = (const float*)d_in[8];
    const float* mean  = (const float*)d_in[9];
    const float* var   = (const float*)d_in[10];
    const float* W1 = (const float*)d_in[11];
    const float* b1 = (const float*)d_in[12];
    const float* W2 = (const float*)d_in[13];
    const float* b2 = (const float*)d_in[14];
    const float* W3 = (const float*)d_in[15];
    const float* b3 = (const float*)d_in[16];
    float* out = (float*)d_out;

    const int SCAN_B = (Nn + 1023) / 1024;

    cudaFuncSetAttribute(k_gemm_mma<16, 0>, cudaFuncAttributeMaxDynamicSharedMemorySize, SMEM_G);
    cudaFuncSetAttribute(k_gemm_mma<4, 1>, cudaFuncAttributeMaxDynamicSharedMemorySize, SMEM_G);

    k_zero_cnt <<<(Nn + 255) / 256, 256>>>();
    k_split_x  <<<(Nn * FIN / 4 + 255) / 256, 256>>>(x);
    k_wsplit   <<<(Ll * Hh * Hh + FIN * Hh + 255) / 256, 256>>>(convW, projW);

    // projection via mma path
    k_gemm_mma<4, 1><<<dim3(MTILES, 2), 256, SMEM_G>>>(0, projb);

    // CSR build
    k_count_edges<<<(Ee + 255) / 256, 256>>>(ei);
    k_scan_block <<<SCAN_B, 1024>>>();
    k_scan_add   <<<SCAN_B, 1024>>>();
    k_csr_fill   <<<(Ee + 255) / 256, 256>>>(ei);

    // 4 GCN layers
    for (int l = 0; l < Ll; l++) {
        k_gemm_mma<16, 0><<<dim3(MTILES, 2), 256, SMEM_G>>>(l, nullptr);
        k_agg_fused<<<(Nn + 3) / 4, 256>>>(convb + l * Hh, gamma + l * Hh, beta + l * Hh,
                                           mean + l * Hh, var + l * Hh);
    }

    // pooling + head
    k_pool<<<Gg, 256>>>(batch);
    k_sgemm<<<dim3(Hh / 64, Gg / 64), 256>>>(W1, b1, Gg, Hh, 2 * Hh, 2);
    k_sgemm<<<dim3((Hh / 2) / 64, Gg / 64), 256>>>(W2, b2, Gg, Hh / 2, Hh, 3);
    k_head3<<<(Gg * Tt + 255) / 256, 256>>>(W3, b3, out);
}